// round 11
// baseline (speedup 1.0000x reference)
#include <cuda_runtime.h>
#include <math.h>
#include <stdint.h>

#define NB   64
#define CCH  64
#define TT   300
#define VV   25
#define ICH  16
#define OCH  64
#define KTAP 9
#define TV   (TT*VV)        /* 7500 */
#define CTV  (CCH*TV)       /* 480000 */
#define NCTV (NB*CTV)       /* 30720000 */
#define BNEPS 1e-5f

#define TILE_P 256
#define NTILE  30           /* tcn tiles */
#define NCTA_B (NB*NTILE)   /* 1920 */
#define YW 456              /* tcn halo width; 456%32==8 */
#define SOW 258

#define AW 136              /* mma A-tile stride */
#define EW 132              /* epilogue / F stride */

#define XW 130              /* k_gcn x-tile stride */
#define NTT 60              /* gcn t-tiles of 5 */
#define NPA (NB*NTT)        /* 3840 BN1 partials per o */
#define NSP 12              /* gram partials per (k,n) */

__device__ __forceinline__ float tf32r(float v) {
    float o; asm("cvt.rna.tf32.f32 %0, %1;" : "=f"(o) : "f"(v)); return o;
}
__device__ __forceinline__ void mma_tf32(float c[4], uint32_t a0, uint32_t a1,
                                         uint32_t a2, uint32_t a3,
                                         uint32_t b0, uint32_t b1) {
    asm volatile(
        "mma.sync.aligned.m16n8k8.row.col.f32.tf32.tf32.f32 "
        "{%0,%1,%2,%3}, {%4,%5,%6,%7}, {%8,%9}, {%0,%1,%2,%3};"
        : "+f"(c[0]), "+f"(c[1]), "+f"(c[2]), "+f"(c[3])
        : "r"(a0), "r"(a1), "r"(a2), "r"(a3), "r"(b0), "r"(b1));
}

// ---------------- scratch (device globals; no allocation) ----------------
__device__ float g_Sp[3*NB*NSP*625];       // gram partials
__device__ float g_S[3*NB*VV*VV];          // attention matrices
__device__ float g_y1[NB*OCH*TV];          // gcn pre-BN
__device__ float g_y3[NB*OCH*TV];          // tcn output
__device__ float g_Wf[8*9*8*32*2];         // tcn B frags [s][kt][nt][lane][2]
__device__ float g_Wfab[8*12*32*2];        // fab packed B frags
__device__ float g_Wdk[3*8*8*32*2];        // Wd packed B frags per k
__device__ float g_pA_s[OCH*NPA];          // BN1 partials
__device__ float g_pA_q[OCH*NPA];
__device__ float g_pB_s[OCH*NCTA_B];       // BN2 partials
__device__ float g_pB_q[OCH*NCTA_B];
__device__ float g_stat[2*OCH*2];          // [which][o][{scale,shift}]

// ---- Wt -> B frags: [s][kt][nt][lane][2] (kt-inner layout) --------------
__global__ void k_prep_wt(const float* __restrict__ Wt)
{
    int j = blockIdx.x*256 + threadIdx.x;
    if (j >= 8*9*8*32) return;
    int l  = j & 31;
    int nt = (j >> 5) & 7;
    int r  = j >> 8;
    int kt = r % 9, s = r / 9;
    int cin = s*8 + (l & 3);
    int o   = nt*8 + (l >> 2);
    g_Wf[j*2 + 0] = tf32r(Wt[(o*64 + cin)*9 + kt]);
    g_Wf[j*2 + 1] = tf32r(Wt[(o*64 + cin + 4)*9 + kt]);
}

// ---- pack Wa/Wb into fab B frags: [s][nt12][lane][2] --------------------
__global__ void k_prep_wfab(const float* __restrict__ Wa,
                            const float* __restrict__ Wb)
{
    int i = blockIdx.x*256 + threadIdx.x;
    if (i >= 8*12*32) return;
    int l  = i & 31;
    int nt = (i >> 5) % 12;
    int s  = i / (32*12);
    int j  = nt*8 + (l >> 2);
    int c0 = s*8 + (l & 3);
    int k = j >> 5, ch = j & 31;
    const float* W = (ch < 16) ? (Wa + (k*16 + ch)*64) : (Wb + (k*16 + ch - 16)*64);
    g_Wfab[i*2 + 0] = tf32r(W[c0]);
    g_Wfab[i*2 + 1] = tf32r(W[c0 + 4]);
}

// ---- pack Wd into per-k B frags: [k][s][nt][lane][2] --------------------
__global__ void k_prep_wd(const float* __restrict__ Wd)
{
    int i = blockIdx.x*256 + threadIdx.x;
    if (i >= 3*8*8*32) return;
    int l  = i & 31;
    int nt = (i >> 5) & 7;
    int s  = (i >> 8) & 7;
    int k  = i >> 11;
    int cin = s*8 + (l & 3);
    int o   = nt*8 + (l >> 2);
    g_Wdk[i*2 + 0] = tf32r(Wd[(k*64 + o)*64 + cin]);
    g_Wdk[i*2 + 1] = tf32r(Wd[(k*64 + o)*64 + cin + 4]);
}

// ========== fused fa/fb conv + gram: no g_fab intermediate ===============
// grid (tc=12, n=64), 256 thr. Per sub (5 x 125 pos): stage x -> mma 96ch
// into smem F -> accumulate gram tiles in regs (t-parity split per thread
// pair, shfl-combined). Gram of sub s-1 overlaps staging of sub s.
__global__ __launch_bounds__(256) void k_fabgram(
    const float* __restrict__ x, const float* __restrict__ ba,
    const float* __restrict__ bb)
{
    extern __shared__ float sm[];
    float* As  = sm;                 // [64][AW] 8704
    float* F   = sm + 64*AW;         // [96][EW] 12672
    float* bsm = F + 96*EW;          // [96]
    int tid = threadIdx.x, w = tid >> 5, l = tid & 31;
    int tc = blockIdx.x, n = blockIdx.y;
    int pbase = tc * 625;

    if (tid < 96) {
        int k = tid >> 5, ch = tid & 31;
        bsm[tid] = (ch < 16) ? ba[k*16 + ch] : bb[k*16 + ch - 16];
    }

    // gram thread mapping: pairs (tid, tid^1) split t by parity
    int u = tid >> 1, half = tid & 1;
    bool gact = u < 75;
    int gk = u / 25, gt = u % 25;
    int vb = (gt / 5) * 5, wb = (gt % 5) * 5;
    const float* Fa0 = F + (gk*32)*EW;        // fa rows base
    const float* Fb0 = F + (gk*32 + 16)*EW;   // fb rows base
    float acc[5][5];
#pragma unroll
    for (int i = 0; i < 5; i++)
#pragma unroll
        for (int j = 0; j < 5; j++) acc[i][j] = 0.f;

    int row = w*16 + (l >> 2);
    int cq  = l & 3;

#pragma unroll 1
    for (int sub = 0; sub < 5; sub++) {
        // ---- phase A: stage x tile; overlap gram of previous sub's F
        int p0 = pbase + sub*125;
        for (int i = tid; i < 64*128; i += 256) {
            int c = i >> 7, p = i & 127;
            As[c*AW + p] = (p < 125) ? tf32r(x[(n*64 + c)*TV + p0 + p]) : 0.f;
        }
        if (sub > 0 && gact) {
#pragma unroll 1
            for (int t = half; t < 5; t += 2) {
#pragma unroll
                for (int o = 0; o < 16; o++) {
                    const float* fa = Fa0 + o*EW + t*25 + vb;
                    const float* fb = Fb0 + o*EW + t*25 + wb;
                    float av[5], bv[5];
#pragma unroll
                    for (int i = 0; i < 5; i++) av[i] = fa[i];
#pragma unroll
                    for (int j = 0; j < 5; j++) bv[j] = fb[j];
#pragma unroll
                    for (int i = 0; i < 5; i++)
#pragma unroll
                        for (int j = 0; j < 5; j++) acc[i][j] += av[i]*bv[j];
                }
            }
        }
        __syncthreads();
        // ---- phase B: mma + write F (with bias)
        float c[12][4];
#pragma unroll
        for (int nt = 0; nt < 12; nt++)
#pragma unroll
            for (int j = 0; j < 4; j++) c[nt][j] = 0.f;
#pragma unroll 1
        for (int s = 0; s < 8; s++) {
            const float* A0 = As + (s*8 + cq)*AW + row;
            uint32_t a0 = __float_as_uint(A0[0]);
            uint32_t a1 = __float_as_uint(A0[8]);
            const float* A2 = A0 + 4*AW;
            uint32_t a2 = __float_as_uint(A2[0]);
            uint32_t a3 = __float_as_uint(A2[8]);
            const float2* B = (const float2*)g_Wfab + s*12*32 + l;
#pragma unroll
            for (int nt = 0; nt < 12; nt++) {
                float2 b = B[nt*32];
                mma_tf32(c[nt], a0, a1, a2, a3,
                         __float_as_uint(b.x), __float_as_uint(b.y));
            }
        }
#pragma unroll
        for (int nt = 0; nt < 12; nt++) {
            int jl = nt*8 + (l & 3)*2;
            int p  = w*16 + (l >> 2);
            float b0 = bsm[jl], b1 = bsm[jl+1];
            F[jl*EW + p]           = c[nt][0] + b0;
            F[(jl+1)*EW + p]       = c[nt][1] + b1;
            F[jl*EW + p + 8]       = c[nt][2] + b0;
            F[(jl+1)*EW + p + 8]   = c[nt][3] + b1;
        }
        __syncthreads();
    }
    // gram of last sub
    if (gact) {
#pragma unroll 1
        for (int t = half; t < 5; t += 2) {
#pragma unroll
            for (int o = 0; o < 16; o++) {
                const float* fa = Fa0 + o*EW + t*25 + vb;
                const float* fb = Fb0 + o*EW + t*25 + wb;
                float av[5], bv[5];
#pragma unroll
                for (int i = 0; i < 5; i++) av[i] = fa[i];
#pragma unroll
                for (int j = 0; j < 5; j++) bv[j] = fb[j];
#pragma unroll
                for (int i = 0; i < 5; i++)
#pragma unroll
                    for (int j = 0; j < 5; j++) acc[i][j] += av[i]*bv[j];
            }
        }
    }
    // combine t-parity halves (lane pairs), store partial
#pragma unroll
    for (int i = 0; i < 5; i++)
#pragma unroll
        for (int j = 0; j < 5; j++)
            acc[i][j] += __shfl_xor_sync(0xffffffffu, acc[i][j], 1);
    if (gact && half == 0) {
        float* sp = g_Sp + ((gk*NB + n)*NSP + tc)*625;
#pragma unroll
        for (int i = 0; i < 5; i++)
#pragma unroll
            for (int j = 0; j < 5; j++)
                sp[(vb + i)*25 + wb + j] = acc[i][j];
    }
}

// ---------------- gram finalize: reduce NSP partials + softmax + A -------
__global__ __launch_bounds__(128) void k_gram_final(
    const float* __restrict__ adj, const float* __restrict__ PA)
{
    int n = blockIdx.x, k = blockIdx.y;
    int tid = threadIdx.x;
    __shared__ float Ss[625];
    const float* sp = g_Sp + (k*NB + n)*NSP*625;
    for (int i = tid; i < 625; i += 128) {
        float s = 0.f;
#pragma unroll
        for (int p = 0; p < NSP; p++) s += sp[p*625 + i];
        Ss[i] = s * (1.f / 4800.f);
    }
    __syncthreads();
    if (tid < 25) {
        int ww = tid;
        float m = -1e30f;
        for (int vv = 0; vv < 25; vv++) m = fmaxf(m, Ss[vv*25 + ww]);
        float s = 0.f;
        for (int vv = 0; vv < 25; vv++) s += expf(Ss[vv*25 + ww] - m);
        float inv = 1.f / s;
        float* Sp = g_S + (k*NB + n)*625;
        for (int vv = 0; vv < 25; vv++)
            Sp[vv*25 + ww] = expf(Ss[vv*25 + ww] - m)*inv
                           + adj[k*625 + vv*25 + ww] + PA[k*625 + vv*25 + ww];
    }
}

// ===== fused GCN: y1 = sum_k Wd[k] @ (x @ S[k]) + bd  (+BN1 partials) ====
__global__ __launch_bounds__(256) void k_gcn(
    const float* __restrict__ x, const float* __restrict__ bd)
{
    extern __shared__ float sm[];
    float* Xs  = sm;                       // [64][XW]   8320
    float* Zs  = sm + 64*XW;               // [64][AW]   8704
    float* Ssm = sm + 64*XW + 64*AW;       // [3][25][28] 2100
    float* bds = Ssm + 2100;               // [64]
    int tid = threadIdx.x, w8 = tid >> 5, l = tid & 31;
    int tt = blockIdx.x, n = blockIdx.y;
    int p0 = tt * 125;

    for (int i = tid; i < 2100; i += 256) {
        int k = i / 700, r = i % 700;
        int v = r / 28, ww = r % 28;
        Ssm[i] = (ww < 25) ? g_S[(k*NB + n)*625 + v*25 + ww] : 0.f;
    }
    if (tid < 64) bds[tid] = bd[tid] + bd[64 + tid] + bd[128 + tid];
    for (int i = tid; i < 8000; i += 256) {
        int c = i / 125, pl = i % 125;
        Xs[c*XW + pl] = x[(n*64 + c)*TV + p0 + pl];
    }
    __syncthreads();

    float acc[8][4];
#pragma unroll
    for (int nt = 0; nt < 8; nt++)
#pragma unroll
        for (int j = 0; j < 4; j++) acc[nt][j] = 0.f;

    int row = w8*16 + (l >> 2);
    int cq  = l & 3;

#pragma unroll 1
    for (int k = 0; k < 3; k++) {
        const float* Sk = Ssm + k*700;
#pragma unroll 1
        for (int rr = tid; rr < 320; rr += 256) {
            int c = rr / 5, tl = rr % 5;
            const float* xr = Xs + c*XW + tl*25;
            float4 av[7];
#pragma unroll
            for (int q = 0; q < 7; q++) av[q] = make_float4(0.f,0.f,0.f,0.f);
#pragma unroll 5
            for (int v = 0; v < 25; v++) {
                float xv = xr[v];
                const float4* Sv = (const float4*)(Sk + v*28);
#pragma unroll
                for (int q = 0; q < 7; q++) {
                    float4 s4 = Sv[q];
                    av[q].x += xv*s4.x; av[q].y += xv*s4.y;
                    av[q].z += xv*s4.z; av[q].w += xv*s4.w;
                }
            }
            float* zp = Zs + c*AW + tl*25;
            const float* af = (const float*)av;
#pragma unroll
            for (int ww = 0; ww < 25; ww++) zp[ww] = tf32r(af[ww]);
        }
        __syncthreads();
#pragma unroll
        for (int s = 0; s < 8; s++) {
            const float* A0 = Zs + (s*8 + cq)*AW + row;
            uint32_t a0 = __float_as_uint(A0[0]);
            uint32_t a1 = __float_as_uint(A0[8]);
            const float* A2 = A0 + 4*AW;
            uint32_t a2 = __float_as_uint(A2[0]);
            uint32_t a3 = __float_as_uint(A2[8]);
            const float2* B = (const float2*)g_Wdk + (k*8 + s)*8*32 + l;
#pragma unroll
            for (int nt = 0; nt < 8; nt++) {
                float2 b = B[nt*32];
                mma_tf32(acc[nt], a0, a1, a2, a3,
                         __float_as_uint(b.x), __float_as_uint(b.y));
            }
        }
        __syncthreads();
    }
    float* Eout = sm;                      // [64][EW]
#pragma unroll
    for (int nt = 0; nt < 8; nt++) {
        int jl = nt*8 + (l & 3)*2;
        int p  = w8*16 + (l >> 2);
        Eout[jl*EW + p]         = acc[nt][0];
        Eout[(jl+1)*EW + p]     = acc[nt][1];
        Eout[jl*EW + p + 8]     = acc[nt][2];
        Eout[(jl+1)*EW + p + 8] = acc[nt][3];
    }
    __syncthreads();
    for (int i = tid; i < 8000; i += 256) {
        int o = i / 125, pl = i % 125;
        g_y1[(n*64 + o)*TV + p0 + pl] = Eout[o*EW + pl] + bds[o];
    }
    if (tid < 64) {
        float s = 0.f, q = 0.f;
        float bv = bds[tid];
        for (int pl = 0; pl < 125; pl++) {
            float u = Eout[tid*EW + pl] + bv;
            s += u; q += u*u;
        }
        g_pA_s[tid*NPA + n*NTT + tt] = s;
        g_pA_q[tid*NPA + n*NTT + tt] = q;
    }
}

// ---------------- BN finalize from partials -------------------------------
__global__ void k_bn_final(const float* __restrict__ g, const float* __restrict__ b,
                           const float* __restrict__ ps, const float* __restrict__ pq,
                           int npart, int which)
{
    int o = blockIdx.x;
    int tid = threadIdx.x;
    __shared__ float red[256];
    float s = 0.f, s2 = 0.f;
    for (int i = tid; i < npart; i += 128) {
        s  += ps[o*npart + i];
        s2 += pq[o*npart + i];
    }
    red[tid] = s; red[128 + tid] = s2;
    __syncthreads();
    for (int st = 64; st > 0; st >>= 1) {
        if (tid < st) {
            red[tid]       += red[tid + st];
            red[128 + tid] += red[128 + tid + st];
        }
        __syncthreads();
    }
    if (tid == 0) {
        const float cnt = (float)(NB*TV);
        float mean = red[0] / cnt;
        float var  = red[128] / cnt - mean*mean;
        float sc = g[o] * rsqrtf(var + BNEPS);
        g_stat[which*128 + o*2 + 0] = sc;
        g_stat[which*128 + o*2 + 1] = b[o] - mean*sc;
    }
}

// ====== tcn: s outer, kt inner, B from L2 (no smem weights, 1 sync) ======
__global__ __launch_bounds__(512, 1) void k_tcn_mma(
    const float* __restrict__ x, const float* __restrict__ bt)
{
    extern __shared__ float sm[];
    float* Ys  = sm;                    // [64][456]
    float* aux = sm + 64*YW;            // [0..63]=bt, [64..191]=bn1 stats
    int tid = threadIdx.x, w = tid >> 5, l = tid & 31;
    int tile = blockIdx.x, n = blockIdx.y;
    int p0 = tile * TILE_P;

    if (tid < 64)  aux[tid] = bt[tid];
    if (tid < 128) aux[64 + tid] = g_stat[tid];
    __syncthreads();

    for (int i = tid; i < 64*YW; i += 512) {
        int cin = i / YW, pl = i % YW;
        int pg = p0 - 100 + pl;
        float val = 0.f;
        if (pg >= 0 && pg < TV) {
            int idx = (n*64 + cin)*TV + pg;
            val = fmaxf(0.f, g_y1[idx]*aux[64 + cin*2] + aux[64 + cin*2 + 1] + x[idx]);
        }
        Ys[i] = tf32r(val);
    }
    __syncthreads();

    float c[8][4];
#pragma unroll
    for (int nt = 0; nt < 8; nt++)
#pragma unroll
        for (int j = 0; j < 4; j++) c[nt][j] = 0.f;

    int rbase0 = w*16 + (l >> 2);
    int cbase  = l & 3;
#pragma unroll 1
    for (int s = 0; s < 8; s++) {
        const float* Abase = Ys + (s*8 + cbase)*YW + rbase0;
#pragma unroll 3
        for (int kt = 0; kt < 9; kt++) {
            const float* A0 = Abase + kt*25;
            uint32_t a0 = __float_as_uint(A0[0]);
            uint32_t a1 = __float_as_uint(A0[8]);
            const float* A2 = A0 + 4*YW;
            uint32_t a2 = __float_as_uint(A2[0]);
            uint32_t a3 = __float_as_uint(A2[8]);
            const float2* B = (const float2*)g_Wf + (s*9 + kt)*8*32 + l;
#pragma unroll
            for (int nt = 0; nt < 8; nt++) {
                float2 b = B[nt*32];
                mma_tf32(c[nt], a0, a1, a2, a3,
                         __float_as_uint(b.x), __float_as_uint(b.y));
            }
        }
    }
    __syncthreads();
    float* Sout = sm;                   // [64][258]
#pragma unroll
    for (int nt = 0; nt < 8; nt++) {
        int o = nt*8 + (l & 3)*2;
        int p = w*16 + (l >> 2);
        Sout[o*SOW + p]         = c[nt][0] + aux[o];
        Sout[(o+1)*SOW + p]     = c[nt][1] + aux[o+1];
        Sout[o*SOW + p + 8]     = c[nt][2] + aux[o];
        Sout[(o+1)*SOW + p + 8] = c[nt][3] + aux[o+1];
    }
    __syncthreads();
    if (tid < 64) {
        float s = 0.f, q = 0.f;
        int lim = TV - p0; if (lim > TILE_P) lim = TILE_P;
        for (int p = 0; p < lim; p++) {
            float u = Sout[tid*SOW + p];
            s += u; q += u*u;
        }
        int cta = n*NTILE + tile;
        g_pB_s[tid*NCTA_B + cta] = s;
        g_pB_q[tid*NCTA_B + cta] = q;
    }
    for (int i = tid; i < 64*TILE_P; i += 512) {
        int o = i >> 8, p = i & 255;
        if (p0 + p < TV)
            g_y3[(n*64 + o)*TV + p0 + p] = Sout[o*SOW + p];
    }
}

// ---- final: out = relu(bn2(y3) + x), float4 -----------------------------
__global__ __launch_bounds__(256) void k_bn_apply4(
    const float4* __restrict__ x4, float4* __restrict__ out4)
{
    const float4* y4 = (const float4*)g_y3;
    long total = NCTV/4;
    for (long i = (long)blockIdx.x*256 + threadIdx.x; i < total; i += (long)gridDim.x*256) {
        int o = (int)((i / 1875) & 63);
        float sc = g_stat[128 + o*2 + 0];
        float sf = g_stat[128 + o*2 + 1];
        float4 y = y4[i], xx = x4[i], r;
        r.x = fmaxf(0.f, y.x*sc + sf + xx.x);
        r.y = fmaxf(0.f, y.y*sc + sf + xx.y);
        r.z = fmaxf(0.f, y.z*sc + sf + xx.z);
        r.w = fmaxf(0.f, y.w*sc + sf + xx.w);
        out4[i] = r;
    }
}

// ---------------- launch --------------------------------------------------
extern "C" void kernel_launch(void* const* d_in, const int* in_sizes, int n_in,
                              void* d_out, int out_size)
{
    const float* x    = (const float*)d_in[0];
    const float* adj  = (const float*)d_in[1];
    const float* PA   = (const float*)d_in[2];
    const float* Wa   = (const float*)d_in[3];
    const float* ba   = (const float*)d_in[4];
    const float* Wb   = (const float*)d_in[5];
    const float* bb   = (const float*)d_in[6];
    const float* Wd   = (const float*)d_in[7];
    const float* bd   = (const float*)d_in[8];
    const float* g1   = (const float*)d_in[9];
    const float* b1   = (const float*)d_in[10];
    const float* Wt   = (const float*)d_in[11];
    const float* bt   = (const float*)d_in[12];
    const float* g2   = (const float*)d_in[13];
    const float* b2   = (const float*)d_in[14];
    float* out = (float*)d_out;

    float *pAs, *pAq, *pBs, *pBq;
    cudaGetSymbolAddress((void**)&pAs, g_pA_s);
    cudaGetSymbolAddress((void**)&pAq, g_pA_q);
    cudaGetSymbolAddress((void**)&pBs, g_pB_s);
    cudaGetSymbolAddress((void**)&pBq, g_pB_q);

    const int tcn_smem  = (64*YW + 192) * 4;                 // 117504 B
    const int fg_smem   = (64*AW + 96*EW + 96) * 4;          // 85888 B
    const int gcn_smem  = (64*XW + 64*AW + 2100 + 64) * 4;   // 76816 B
    static int smem_set = 0;
    if (!smem_set) {
        cudaFuncSetAttribute(k_tcn_mma,
                             cudaFuncAttributeMaxDynamicSharedMemorySize, tcn_smem);
        cudaFuncSetAttribute(k_fabgram,
                             cudaFuncAttributeMaxDynamicSharedMemorySize, fg_smem);
        cudaFuncSetAttribute(k_gcn,
                             cudaFuncAttributeMaxDynamicSharedMemorySize, gcn_smem);
        smem_set = 1;
    }

    k_prep_wt<<<72, 256>>>(Wt);
    k_prep_wfab<<<12, 256>>>(Wa, Wb);
    k_prep_wd<<<24, 256>>>(Wd);

    k_fabgram<<<dim3(NSP, NB), 256, fg_smem>>>(x, ba, bb);
    k_gram_final<<<dim3(NB, 3), 128>>>(adj, PA);
    k_gcn<<<dim3(NTT, NB), 256, gcn_smem>>>(x, bd);

    k_bn_final<<<64, 128>>>(g1, b1, pAs, pAq, NPA, 0);

    k_tcn_mma<<<dim3(NTILE, NB), 512, tcn_smem>>>(x, bt);

    k_bn_final<<<64, 128>>>(g2, b2, pBs, pBq, NCTA_B, 1);

    k_bn_apply4<<<8192, 256>>>((const float4*)x, (float4*)out);

    // second tuple element: adj_mat passthrough
    long tail = (long)out_size - (long)NCTV;
    if (tail > 0) {
        long cnt = tail < 1875 ? tail : 1875;
        cudaMemcpyAsync(out + NCTV, d_in[1], cnt * sizeof(float),
                        cudaMemcpyDeviceToDevice);
    }
}

// round 12
// speedup vs baseline: 1.1981x; 1.1981x over previous
#include <cuda_runtime.h>
#include <math.h>
#include <stdint.h>

#define NB   64
#define CCH  64
#define TT   300
#define VV   25
#define ICH  16
#define OCH  64
#define KTAP 9
#define TV   (TT*VV)        /* 7500 */
#define CTV  (CCH*TV)       /* 480000 */
#define NCTV (NB*CTV)       /* 30720000 */
#define BNEPS 1e-5f

#define TILE_P 256
#define NTILE  30           /* tcn tiles */
#define NCTA_B (NB*NTILE)   /* 1920 */
#define YW 456              /* tcn halo width; 456%32==8 */
#define SOW 258

#define AW 136              /* mma A-tile stride */
#define EW 132              /* epilogue / F stride */

#define XW 130              /* k_gcn x-tile stride */
#define NTT 60              /* gcn t-tiles of 5 */
#define NPA (NB*NTT)        /* 3840 BN1 partials per o */
#define NSP 60              /* gram partials per (k,n) */

__device__ __forceinline__ float tf32r(float v) {
    float o; asm("cvt.rna.tf32.f32 %0, %1;" : "=f"(o) : "f"(v)); return o;
}
__device__ __forceinline__ void mma_tf32(float c[4], uint32_t a0, uint32_t a1,
                                         uint32_t a2, uint32_t a3,
                                         uint32_t b0, uint32_t b1) {
    asm volatile(
        "mma.sync.aligned.m16n8k8.row.col.f32.tf32.tf32.f32 "
        "{%0,%1,%2,%3}, {%4,%5,%6,%7}, {%8,%9}, {%0,%1,%2,%3};"
        : "+f"(c[0]), "+f"(c[1]), "+f"(c[2]), "+f"(c[3])
        : "r"(a0), "r"(a1), "r"(a2), "r"(a3), "r"(b0), "r"(b1));
}

// ---------------- scratch (device globals; no allocation) ----------------
__device__ float g_Sp[3*NB*NSP*625];       // gram partials
__device__ float g_S[3*NB*VV*VV];          // attention matrices
__device__ float g_y1[NB*OCH*TV];          // gcn pre-BN
__device__ float g_y3[NB*OCH*TV];          // tcn output
__device__ float g_Wf[8*9*8*32*2];         // tcn B frags [s][kt][nt][lane][2]
__device__ float g_Wfab[8*12*32*2];        // fab packed B frags
__device__ float g_Wdk[3*8*8*32*2];        // Wd packed B frags per k
__device__ float g_pA_s[OCH*NPA];          // BN1 partials
__device__ float g_pA_q[OCH*NPA];
__device__ float g_pB_s[OCH*NCTA_B];       // BN2 partials
__device__ float g_pB_q[OCH*NCTA_B];
__device__ float g_stat[2*OCH*2];          // [which][o][{scale,shift}]

// ---- Wt -> B frags: [s][kt][nt][lane][2] (kt-inner layout) --------------
__global__ void k_prep_wt(const float* __restrict__ Wt)
{
    int j = blockIdx.x*256 + threadIdx.x;
    if (j >= 8*9*8*32) return;
    int l  = j & 31;
    int nt = (j >> 5) & 7;
    int r  = j >> 8;
    int kt = r % 9, s = r / 9;
    int cin = s*8 + (l & 3);
    int o   = nt*8 + (l >> 2);
    g_Wf[j*2 + 0] = tf32r(Wt[(o*64 + cin)*9 + kt]);
    g_Wf[j*2 + 1] = tf32r(Wt[(o*64 + cin + 4)*9 + kt]);
}

// ---- pack Wa/Wb into fab B frags: [s][nt12][lane][2] --------------------
__global__ void k_prep_wfab(const float* __restrict__ Wa,
                            const float* __restrict__ Wb)
{
    int i = blockIdx.x*256 + threadIdx.x;
    if (i >= 8*12*32) return;
    int l  = i & 31;
    int nt = (i >> 5) % 12;
    int s  = i / (32*12);
    int j  = nt*8 + (l >> 2);
    int c0 = s*8 + (l & 3);
    int k = j >> 5, ch = j & 31;
    const float* W = (ch < 16) ? (Wa + (k*16 + ch)*64) : (Wb + (k*16 + ch - 16)*64);
    g_Wfab[i*2 + 0] = tf32r(W[c0]);
    g_Wfab[i*2 + 1] = tf32r(W[c0 + 4]);
}

// ---- pack Wd into per-k B frags: [k][s][nt][lane][2] --------------------
__global__ void k_prep_wd(const float* __restrict__ Wd)
{
    int i = blockIdx.x*256 + threadIdx.x;
    if (i >= 3*8*8*32) return;
    int l  = i & 31;
    int nt = (i >> 5) & 7;
    int s  = (i >> 8) & 7;
    int k  = i >> 11;
    int cin = s*8 + (l & 3);
    int o   = nt*8 + (l >> 2);
    g_Wdk[i*2 + 0] = tf32r(Wd[(k*64 + o)*64 + cin]);
    g_Wdk[i*2 + 1] = tf32r(Wd[(k*64 + o)*64 + cin + 4]);
}

// ==== fused fa/fb conv + per-tile gram, single-shot, grid 3840 ===========
// 125-pos tiles (= exactly 5 t-rows): stage x -> mma 96ch -> E(+bias) in
// smem -> gram partial for these 5 t directly from E. No g_fab.
__global__ __launch_bounds__(256, 3) void k_fabgram(
    const float* __restrict__ x, const float* __restrict__ ba,
    const float* __restrict__ bb)
{
    extern __shared__ float sm[];
    float* As  = sm;                 // [64][AW] 8704 (phase 1)
    float* E   = sm;                 // [96][EW] 12672 (phase 2, aliases)
    float* bsm = sm + 12672;         // [96]
    int tid = threadIdx.x, w = tid >> 5, l = tid & 31;
    int tile = blockIdx.x, n = blockIdx.y;
    int p0 = tile * 125;

    if (tid < 96) {
        int k = tid >> 5, ch = tid & 31;
        bsm[tid] = (ch < 16) ? ba[k*16 + ch] : bb[k*16 + ch - 16];
    }
    for (int i = tid; i < 64*128; i += 256) {
        int c = i >> 7, p = i & 127;
        As[c*AW + p] = (p < 125) ? tf32r(x[(n*64 + c)*TV + p0 + p]) : 0.f;
    }
    __syncthreads();

    int row = w*16 + (l >> 2);
    int cq  = l & 3;

    float c[12][4];
#pragma unroll
    for (int nt = 0; nt < 12; nt++)
#pragma unroll
        for (int j = 0; j < 4; j++) c[nt][j] = 0.f;
#pragma unroll 1
    for (int s = 0; s < 8; s++) {
        const float* A0 = As + (s*8 + cq)*AW + row;
        uint32_t a0 = __float_as_uint(A0[0]);
        uint32_t a1 = __float_as_uint(A0[8]);
        const float* A2 = A0 + 4*AW;
        uint32_t a2 = __float_as_uint(A2[0]);
        uint32_t a3 = __float_as_uint(A2[8]);
        const float2* B = (const float2*)g_Wfab + s*12*32 + l;
#pragma unroll
        for (int nt = 0; nt < 12; nt++) {
            float2 b = B[nt*32];
            mma_tf32(c[nt], a0, a1, a2, a3,
                     __float_as_uint(b.x), __float_as_uint(b.y));
        }
    }
    __syncthreads();                // As consumed -> reuse as E
#pragma unroll
    for (int nt = 0; nt < 12; nt++) {
        int jl = nt*8 + (l & 3)*2;
        int p  = w*16 + (l >> 2);
        float b0 = bsm[jl], b1 = bsm[jl+1];
        E[jl*EW + p]           = c[nt][0] + b0;
        E[(jl+1)*EW + p]       = c[nt][1] + b1;
        E[jl*EW + p + 8]       = c[nt][2] + b0;
        E[(jl+1)*EW + p + 8]   = c[nt][3] + b1;
    }
    __syncthreads();
    // ---- gram partial over this tile's 5 t-rows, from E in smem
    // pairs (tid, tid^1) split t by parity; u<75 -> (k, 5x5 tile)
    int u = tid >> 1, half = tid & 1;
    bool gact = u < 75;
    float acc[5][5];
#pragma unroll
    for (int i = 0; i < 5; i++)
#pragma unroll
        for (int j = 0; j < 5; j++) acc[i][j] = 0.f;
    int gk = u / 25, gt = u % 25;
    int vb = (gt / 5) * 5, wb = (gt % 5) * 5;
    if (gact) {
        const float* Fa0 = E + (gk*32)*EW;
        const float* Fb0 = E + (gk*32 + 16)*EW;
#pragma unroll 1
        for (int t = half; t < 5; t += 2) {
#pragma unroll
            for (int o = 0; o < 16; o++) {
                const float* fa = Fa0 + o*EW + t*25 + vb;
                const float* fb = Fb0 + o*EW + t*25 + wb;
                float av[5], bv[5];
#pragma unroll
                for (int i = 0; i < 5; i++) av[i] = fa[i];
#pragma unroll
                for (int j = 0; j < 5; j++) bv[j] = fb[j];
#pragma unroll
                for (int i = 0; i < 5; i++)
#pragma unroll
                    for (int j = 0; j < 5; j++) acc[i][j] += av[i]*bv[j];
            }
        }
    }
#pragma unroll
    for (int i = 0; i < 5; i++)
#pragma unroll
        for (int j = 0; j < 5; j++)
            acc[i][j] += __shfl_xor_sync(0xffffffffu, acc[i][j], 1);
    if (gact && half == 0) {
        float* sp = g_Sp + ((gk*NB + n)*NSP + tile)*625;
#pragma unroll
        for (int i = 0; i < 5; i++)
#pragma unroll
            for (int j = 0; j < 5; j++)
                sp[(vb + i)*25 + wb + j] = acc[i][j];
    }
}

// ---------------- gram finalize: reduce NSP partials + softmax + A -------
__global__ __launch_bounds__(128) void k_gram_final(
    const float* __restrict__ adj, const float* __restrict__ PA)
{
    int n = blockIdx.x, k = blockIdx.y;
    int tid = threadIdx.x;
    __shared__ float Ss[625];
    const float* sp = g_Sp + (k*NB + n)*NSP*625;
    for (int i = tid; i < 625; i += 128) {
        float s = 0.f;
#pragma unroll 6
        for (int p = 0; p < NSP; p++) s += sp[p*625 + i];
        Ss[i] = s * (1.f / 4800.f);
    }
    __syncthreads();
    if (tid < 25) {
        int ww = tid;
        float m = -1e30f;
        for (int vv = 0; vv < 25; vv++) m = fmaxf(m, Ss[vv*25 + ww]);
        float s = 0.f;
        for (int vv = 0; vv < 25; vv++) s += expf(Ss[vv*25 + ww] - m);
        float inv = 1.f / s;
        float* Sp = g_S + (k*NB + n)*625;
        for (int vv = 0; vv < 25; vv++)
            Sp[vv*25 + ww] = expf(Ss[vv*25 + ww] - m)*inv
                           + adj[k*625 + vv*25 + ww] + PA[k*625 + vv*25 + ww];
    }
}

// ===== fused GCN: y1 = sum_k Wd[k] @ (x @ S[k]) + bd  (+BN1 partials) ====
__global__ __launch_bounds__(256) void k_gcn(
    const float* __restrict__ x, const float* __restrict__ bd)
{
    extern __shared__ float sm[];
    float* Xs  = sm;                       // [64][XW]   8320
    float* Zs  = sm + 64*XW;               // [64][AW]   8704
    float* Ssm = sm + 64*XW + 64*AW;       // [3][25][28] 2100
    float* bds = Ssm + 2100;               // [64]
    int tid = threadIdx.x, w8 = tid >> 5, l = tid & 31;
    int tt = blockIdx.x, n = blockIdx.y;
    int p0 = tt * 125;

    for (int i = tid; i < 2100; i += 256) {
        int k = i / 700, r = i % 700;
        int v = r / 28, ww = r % 28;
        Ssm[i] = (ww < 25) ? g_S[(k*NB + n)*625 + v*25 + ww] : 0.f;
    }
    if (tid < 64) bds[tid] = bd[tid] + bd[64 + tid] + bd[128 + tid];
    for (int i = tid; i < 8000; i += 256) {
        int c = i / 125, pl = i % 125;
        Xs[c*XW + pl] = x[(n*64 + c)*TV + p0 + pl];
    }
    __syncthreads();

    float acc[8][4];
#pragma unroll
    for (int nt = 0; nt < 8; nt++)
#pragma unroll
        for (int j = 0; j < 4; j++) acc[nt][j] = 0.f;

    int row = w8*16 + (l >> 2);
    int cq  = l & 3;

#pragma unroll 1
    for (int k = 0; k < 3; k++) {
        const float* Sk = Ssm + k*700;
#pragma unroll 1
        for (int rr = tid; rr < 320; rr += 256) {
            int c = rr / 5, tl = rr % 5;
            const float* xr = Xs + c*XW + tl*25;
            float4 av[7];
#pragma unroll
            for (int q = 0; q < 7; q++) av[q] = make_float4(0.f,0.f,0.f,0.f);
#pragma unroll 5
            for (int v = 0; v < 25; v++) {
                float xv = xr[v];
                const float4* Sv = (const float4*)(Sk + v*28);
#pragma unroll
                for (int q = 0; q < 7; q++) {
                    float4 s4 = Sv[q];
                    av[q].x += xv*s4.x; av[q].y += xv*s4.y;
                    av[q].z += xv*s4.z; av[q].w += xv*s4.w;
                }
            }
            float* zp = Zs + c*AW + tl*25;
            const float* af = (const float*)av;
#pragma unroll
            for (int ww = 0; ww < 25; ww++) zp[ww] = tf32r(af[ww]);
        }
        __syncthreads();
#pragma unroll
        for (int s = 0; s < 8; s++) {
            const float* A0 = Zs + (s*8 + cq)*AW + row;
            uint32_t a0 = __float_as_uint(A0[0]);
            uint32_t a1 = __float_as_uint(A0[8]);
            const float* A2 = A0 + 4*AW;
            uint32_t a2 = __float_as_uint(A2[0]);
            uint32_t a3 = __float_as_uint(A2[8]);
            const float2* B = (const float2*)g_Wdk + (k*8 + s)*8*32 + l;
#pragma unroll
            for (int nt = 0; nt < 8; nt++) {
                float2 b = B[nt*32];
                mma_tf32(acc[nt], a0, a1, a2, a3,
                         __float_as_uint(b.x), __float_as_uint(b.y));
            }
        }
        __syncthreads();
    }
    float* Eout = sm;                      // [64][EW]
#pragma unroll
    for (int nt = 0; nt < 8; nt++) {
        int jl = nt*8 + (l & 3)*2;
        int p  = w8*16 + (l >> 2);
        Eout[jl*EW + p]         = acc[nt][0];
        Eout[(jl+1)*EW + p]     = acc[nt][1];
        Eout[jl*EW + p + 8]     = acc[nt][2];
        Eout[(jl+1)*EW + p + 8] = acc[nt][3];
    }
    __syncthreads();
    for (int i = tid; i < 8000; i += 256) {
        int o = i / 125, pl = i % 125;
        g_y1[(n*64 + o)*TV + p0 + pl] = Eout[o*EW + pl] + bds[o];
    }
    if (tid < 64) {
        float s = 0.f, q = 0.f;
        float bv = bds[tid];
        for (int pl = 0; pl < 125; pl++) {
            float u = Eout[tid*EW + pl] + bv;
            s += u; q += u*u;
        }
        g_pA_s[tid*NPA + n*NTT + tt] = s;
        g_pA_q[tid*NPA + n*NTT + tt] = q;
    }
}

// ---------------- BN finalize from partials -------------------------------
__global__ void k_bn_final(const float* __restrict__ g, const float* __restrict__ b,
                           const float* __restrict__ ps, const float* __restrict__ pq,
                           int npart, int which)
{
    int o = blockIdx.x;
    int tid = threadIdx.x;
    __shared__ float red[256];
    float s = 0.f, s2 = 0.f;
    for (int i = tid; i < npart; i += 128) {
        s  += ps[o*npart + i];
        s2 += pq[o*npart + i];
    }
    red[tid] = s; red[128 + tid] = s2;
    __syncthreads();
    for (int st = 64; st > 0; st >>= 1) {
        if (tid < st) {
            red[tid]       += red[tid + st];
            red[128 + tid] += red[128 + tid + st];
        }
        __syncthreads();
    }
    if (tid == 0) {
        const float cnt = (float)(NB*TV);
        float mean = red[0] / cnt;
        float var  = red[128] / cnt - mean*mean;
        float sc = g[o] * rsqrtf(var + BNEPS);
        g_stat[which*128 + o*2 + 0] = sc;
        g_stat[which*128 + o*2 + 1] = b[o] - mean*sc;
    }
}

// ====== tcn: s outer, kt inner, B from L2 (no smem weights, 1 sync) ======
__global__ __launch_bounds__(512, 1) void k_tcn_mma(
    const float* __restrict__ x, const float* __restrict__ bt)
{
    extern __shared__ float sm[];
    float* Ys  = sm;                    // [64][456]
    float* aux = sm + 64*YW;            // [0..63]=bt, [64..191]=bn1 stats
    int tid = threadIdx.x, w = tid >> 5, l = tid & 31;
    int tile = blockIdx.x, n = blockIdx.y;
    int p0 = tile * TILE_P;

    if (tid < 64)  aux[tid] = bt[tid];
    if (tid < 128) aux[64 + tid] = g_stat[tid];
    __syncthreads();

    for (int i = tid; i < 64*YW; i += 512) {
        int cin = i / YW, pl = i % YW;
        int pg = p0 - 100 + pl;
        float val = 0.f;
        if (pg >= 0 && pg < TV) {
            int idx = (n*64 + cin)*TV + pg;
            val = fmaxf(0.f, g_y1[idx]*aux[64 + cin*2] + aux[64 + cin*2 + 1] + x[idx]);
        }
        Ys[i] = tf32r(val);
    }
    __syncthreads();

    float c[8][4];
#pragma unroll
    for (int nt = 0; nt < 8; nt++)
#pragma unroll
        for (int j = 0; j < 4; j++) c[nt][j] = 0.f;

    int rbase0 = w*16 + (l >> 2);
    int cbase  = l & 3;
#pragma unroll 1
    for (int s = 0; s < 8; s++) {
        const float* Abase = Ys + (s*8 + cbase)*YW + rbase0;
#pragma unroll 3
        for (int kt = 0; kt < 9; kt++) {
            const float* A0 = Abase + kt*25;
            uint32_t a0 = __float_as_uint(A0[0]);
            uint32_t a1 = __float_as_uint(A0[8]);
            const float* A2 = A0 + 4*YW;
            uint32_t a2 = __float_as_uint(A2[0]);
            uint32_t a3 = __float_as_uint(A2[8]);
            const float2* B = (const float2*)g_Wf + (s*9 + kt)*8*32 + l;
#pragma unroll
            for (int nt = 0; nt < 8; nt++) {
                float2 b = B[nt*32];
                mma_tf32(c[nt], a0, a1, a2, a3,
                         __float_as_uint(b.x), __float_as_uint(b.y));
            }
        }
    }
    __syncthreads();
    float* Sout = sm;                   // [64][258]
#pragma unroll
    for (int nt = 0; nt < 8; nt++) {
        int o = nt*8 + (l & 3)*2;
        int p = w*16 + (l >> 2);
        Sout[o*SOW + p]         = c[nt][0] + aux[o];
        Sout[(o+1)*SOW + p]     = c[nt][1] + aux[o+1];
        Sout[o*SOW + p + 8]     = c[nt][2] + aux[o];
        Sout[(o+1)*SOW + p + 8] = c[nt][3] + aux[o+1];
    }
    __syncthreads();
    if (tid < 64) {
        float s = 0.f, q = 0.f;
        int lim = TV - p0; if (lim > TILE_P) lim = TILE_P;
        for (int p = 0; p < lim; p++) {
            float u = Sout[tid*SOW + p];
            s += u; q += u*u;
        }
        int cta = n*NTILE + tile;
        g_pB_s[tid*NCTA_B + cta] = s;
        g_pB_q[tid*NCTA_B + cta] = q;
    }
    for (int i = tid; i < 64*TILE_P; i += 512) {
        int o = i >> 8, p = i & 255;
        if (p0 + p < TV)
            g_y3[(n*64 + o)*TV + p0 + p] = Sout[o*SOW + p];
    }
}

// ---- final: out = relu(bn2(y3) + x), float4 -----------------------------
__global__ __launch_bounds__(256) void k_bn_apply4(
    const float4* __restrict__ x4, float4* __restrict__ out4)
{
    const float4* y4 = (const float4*)g_y3;
    long total = NCTV/4;
    for (long i = (long)blockIdx.x*256 + threadIdx.x; i < total; i += (long)gridDim.x*256) {
        int o = (int)((i / 1875) & 63);
        float sc = g_stat[128 + o*2 + 0];
        float sf = g_stat[128 + o*2 + 1];
        float4 y = y4[i], xx = x4[i], r;
        r.x = fmaxf(0.f, y.x*sc + sf + xx.x);
        r.y = fmaxf(0.f, y.y*sc + sf + xx.y);
        r.z = fmaxf(0.f, y.z*sc + sf + xx.z);
        r.w = fmaxf(0.f, y.w*sc + sf + xx.w);
        out4[i] = r;
    }
}

// ---------------- launch --------------------------------------------------
extern "C" void kernel_launch(void* const* d_in, const int* in_sizes, int n_in,
                              void* d_out, int out_size)
{
    const float* x    = (const float*)d_in[0];
    const float* adj  = (const float*)d_in[1];
    const float* PA   = (const float*)d_in[2];
    const float* Wa   = (const float*)d_in[3];
    const float* ba   = (const float*)d_in[4];
    const float* Wb   = (const float*)d_in[5];
    const float* bb   = (const float*)d_in[6];
    const float* Wd   = (const float*)d_in[7];
    const float* bd   = (const float*)d_in[8];
    const float* g1   = (const float*)d_in[9];
    const float* b1   = (const float*)d_in[10];
    const float* Wt   = (const float*)d_in[11];
    const float* bt   = (const float*)d_in[12];
    const float* g2   = (const float*)d_in[13];
    const float* b2   = (const float*)d_in[14];
    float* out = (float*)d_out;

    float *pAs, *pAq, *pBs, *pBq;
    cudaGetSymbolAddress((void**)&pAs, g_pA_s);
    cudaGetSymbolAddress((void**)&pAq, g_pA_q);
    cudaGetSymbolAddress((void**)&pBs, g_pB_s);
    cudaGetSymbolAddress((void**)&pBq, g_pB_q);

    const int tcn_smem  = (64*YW + 192) * 4;                 // 117504 B
    const int fg_smem   = (12672 + 96) * 4;                  // 51072 B
    const int gcn_smem  = (64*XW + 64*AW + 2100 + 64) * 4;   // 76816 B
    static int smem_set = 0;
    if (!smem_set) {
        cudaFuncSetAttribute(k_tcn_mma,
                             cudaFuncAttributeMaxDynamicSharedMemorySize, tcn_smem);
        cudaFuncSetAttribute(k_fabgram,
                             cudaFuncAttributeMaxDynamicSharedMemorySize, fg_smem);
        cudaFuncSetAttribute(k_gcn,
                             cudaFuncAttributeMaxDynamicSharedMemorySize, gcn_smem);
        smem_set = 1;
    }

    k_prep_wt<<<72, 256>>>(Wt);
    k_prep_wfab<<<12, 256>>>(Wa, Wb);
    k_prep_wd<<<24, 256>>>(Wd);

    k_fabgram<<<dim3(NSP, NB), 256, fg_smem>>>(x, ba, bb);
    k_gram_final<<<dim3(NB, 3), 128>>>(adj, PA);
    k_gcn<<<dim3(NTT, NB), 256, gcn_smem>>>(x, bd);

    k_bn_final<<<64, 128>>>(g1, b1, pAs, pAq, NPA, 0);

    k_tcn_mma<<<dim3(NTILE, NB), 512, tcn_smem>>>(x, bt);

    k_bn_final<<<64, 128>>>(g2, b2, pBs, pBq, NCTA_B, 1);

    k_bn_apply4<<<8192, 256>>>((const float4*)x, (float4*)out);

    // second tuple element: adj_mat passthrough
    long tail = (long)out_size - (long)NCTV;
    if (tail > 0) {
        long cnt = tail < 1875 ? tail : 1875;
        cudaMemcpyAsync(out + NCTV, d_in[1], cnt * sizeof(float),
                        cudaMemcpyDeviceToDevice);
    }
}

// round 13
// speedup vs baseline: 1.2023x; 1.0035x over previous
#include <cuda_runtime.h>
#include <math.h>
#include <stdint.h>

#define NB   64
#define CCH  64
#define TT   300
#define VV   25
#define ICH  16
#define OCH  64
#define KTAP 9
#define TV   (TT*VV)        /* 7500 */
#define CTV  (CCH*TV)       /* 480000 */
#define NCTV (NB*CTV)       /* 30720000 */
#define BNEPS 1e-5f

#define TILE_P 256
#define NTILE  30           /* tcn tiles */
#define NCTA_B (NB*NTILE)   /* 1920 */
#define YW 456              /* tcn halo width; 456%32==8 */
#define SOW 258

#define AW 136              /* mma A-tile stride */
#define EW 132              /* epilogue / F stride */

#define XW 124              /* k_gcn x-tile stride (occ-3 fit) */
#define NTT 60              /* gcn t-tiles of 5 */
#define NPA (NB*NTT)        /* 3840 BN1 partials per o */
#define NSP 60              /* gram partials per (k,n) */

__device__ __forceinline__ float tf32r(float v) {
    float o; asm("cvt.rna.tf32.f32 %0, %1;" : "=f"(o) : "f"(v)); return o;
}
__device__ __forceinline__ void mma_tf32(float c[4], uint32_t a0, uint32_t a1,
                                         uint32_t a2, uint32_t a3,
                                         uint32_t b0, uint32_t b1) {
    asm volatile(
        "mma.sync.aligned.m16n8k8.row.col.f32.tf32.tf32.f32 "
        "{%0,%1,%2,%3}, {%4,%5,%6,%7}, {%8,%9}, {%0,%1,%2,%3};"
        : "+f"(c[0]), "+f"(c[1]), "+f"(c[2]), "+f"(c[3])
        : "r"(a0), "r"(a1), "r"(a2), "r"(a3), "r"(b0), "r"(b1));
}

// ---------------- scratch (device globals; no allocation) ----------------
__device__ float g_Sp[3*NB*NSP*625];       // gram partials
__device__ float g_S[3*NB*VV*VV];          // attention matrices
__device__ float g_y1[NB*OCH*TV];          // gcn pre-BN
__device__ float g_y3[NB*OCH*TV];          // tcn output
__device__ float g_Wf[8*9*8*32*2];         // tcn B frags [s][kt][nt][lane][2]
__device__ float g_Wfab[8*12*32*2];        // fab packed B frags
__device__ float g_Wdk[3*8*8*32*2];        // Wd packed B frags per k
__device__ float g_pA_s[OCH*NPA];          // BN1 partials
__device__ float g_pA_q[OCH*NPA];
__device__ float g_pB_s[OCH*NCTA_B];       // BN2 partials
__device__ float g_pB_q[OCH*NCTA_B];
__device__ float g_stat[2*OCH*2];          // [which][o][{scale,shift}]

// ---- Wt -> B frags: [s][kt][nt][lane][2] (kt-inner layout) --------------
__global__ void k_prep_wt(const float* __restrict__ Wt)
{
    int j = blockIdx.x*256 + threadIdx.x;
    if (j >= 8*9*8*32) return;
    int l  = j & 31;
    int nt = (j >> 5) & 7;
    int r  = j >> 8;
    int kt = r % 9, s = r / 9;
    int cin = s*8 + (l & 3);
    int o   = nt*8 + (l >> 2);
    g_Wf[j*2 + 0] = tf32r(Wt[(o*64 + cin)*9 + kt]);
    g_Wf[j*2 + 1] = tf32r(Wt[(o*64 + cin + 4)*9 + kt]);
}

// ---- pack Wa/Wb into fab B frags: [s][nt12][lane][2] --------------------
__global__ void k_prep_wfab(const float* __restrict__ Wa,
                            const float* __restrict__ Wb)
{
    int i = blockIdx.x*256 + threadIdx.x;
    if (i >= 8*12*32) return;
    int l  = i & 31;
    int nt = (i >> 5) % 12;
    int s  = i / (32*12);
    int j  = nt*8 + (l >> 2);
    int c0 = s*8 + (l & 3);
    int k = j >> 5, ch = j & 31;
    const float* W = (ch < 16) ? (Wa + (k*16 + ch)*64) : (Wb + (k*16 + ch - 16)*64);
    g_Wfab[i*2 + 0] = tf32r(W[c0]);
    g_Wfab[i*2 + 1] = tf32r(W[c0 + 4]);
}

// ---- pack Wd into per-k B frags: [k][s][nt][lane][2] --------------------
__global__ void k_prep_wd(const float* __restrict__ Wd)
{
    int i = blockIdx.x*256 + threadIdx.x;
    if (i >= 3*8*8*32) return;
    int l  = i & 31;
    int nt = (i >> 5) & 7;
    int s  = (i >> 8) & 7;
    int k  = i >> 11;
    int cin = s*8 + (l & 3);
    int o   = nt*8 + (l >> 2);
    g_Wdk[i*2 + 0] = tf32r(Wd[(k*64 + o)*64 + cin]);
    g_Wdk[i*2 + 1] = tf32r(Wd[(k*64 + o)*64 + cin + 4]);
}

// ==== fused fa/fb conv + per-tile gram, single-shot, grid 3840, occ 4 ====
__global__ __launch_bounds__(256, 4) void k_fabgram(
    const float* __restrict__ x, const float* __restrict__ ba,
    const float* __restrict__ bb)
{
    extern __shared__ float sm[];
    float* As  = sm;                 // [64][AW] 8704 (phase 1)
    float* E   = sm;                 // [96][EW] 12672 (phase 2, aliases)
    float* bsm = sm + 12672;         // [96]
    int tid = threadIdx.x, w = tid >> 5, l = tid & 31;
    int tile = blockIdx.x, n = blockIdx.y;
    int p0 = tile * 125;

    if (tid < 96) {
        int k = tid >> 5, ch = tid & 31;
        bsm[tid] = (ch < 16) ? ba[k*16 + ch] : bb[k*16 + ch - 16];
    }
    for (int i = tid; i < 64*128; i += 256) {
        int c = i >> 7, p = i & 127;
        As[c*AW + p] = (p < 125) ? tf32r(x[(n*64 + c)*TV + p0 + p]) : 0.f;
    }
    __syncthreads();

    int row = w*16 + (l >> 2);
    int cq  = l & 3;

    float c[12][4];
#pragma unroll
    for (int nt = 0; nt < 12; nt++)
#pragma unroll
        for (int j = 0; j < 4; j++) c[nt][j] = 0.f;
#pragma unroll 1
    for (int s = 0; s < 8; s++) {
        const float* A0 = As + (s*8 + cq)*AW + row;
        uint32_t a0 = __float_as_uint(A0[0]);
        uint32_t a1 = __float_as_uint(A0[8]);
        const float* A2 = A0 + 4*AW;
        uint32_t a2 = __float_as_uint(A2[0]);
        uint32_t a3 = __float_as_uint(A2[8]);
        const float2* B = (const float2*)g_Wfab + s*12*32 + l;
#pragma unroll
        for (int nt = 0; nt < 12; nt++) {
            float2 b = B[nt*32];
            mma_tf32(c[nt], a0, a1, a2, a3,
                     __float_as_uint(b.x), __float_as_uint(b.y));
        }
    }
    __syncthreads();                // As consumed -> reuse as E
#pragma unroll
    for (int nt = 0; nt < 12; nt++) {
        int jl = nt*8 + (l & 3)*2;
        int p  = w*16 + (l >> 2);
        float b0 = bsm[jl], b1 = bsm[jl+1];
        E[jl*EW + p]           = c[nt][0] + b0;
        E[(jl+1)*EW + p]       = c[nt][1] + b1;
        E[jl*EW + p + 8]       = c[nt][2] + b0;
        E[(jl+1)*EW + p + 8]   = c[nt][3] + b1;
    }
    __syncthreads();
    // ---- gram partial over this tile's 5 t-rows, from E in smem
    int u = tid >> 1, half = tid & 1;
    bool gact = u < 75;
    float acc[5][5];
#pragma unroll
    for (int i = 0; i < 5; i++)
#pragma unroll
        for (int j = 0; j < 5; j++) acc[i][j] = 0.f;
    int gk = u / 25, gt = u % 25;
    int vb = (gt / 5) * 5, wb = (gt % 5) * 5;
    if (gact) {
        const float* Fa0 = E + (gk*32)*EW;
        const float* Fb0 = E + (gk*32 + 16)*EW;
#pragma unroll 1
        for (int t = half; t < 5; t += 2) {
#pragma unroll
            for (int o = 0; o < 16; o++) {
                const float* fa = Fa0 + o*EW + t*25 + vb;
                const float* fb = Fb0 + o*EW + t*25 + wb;
                float av[5], bv[5];
#pragma unroll
                for (int i = 0; i < 5; i++) av[i] = fa[i];
#pragma unroll
                for (int j = 0; j < 5; j++) bv[j] = fb[j];
#pragma unroll
                for (int i = 0; i < 5; i++)
#pragma unroll
                    for (int j = 0; j < 5; j++) acc[i][j] += av[i]*bv[j];
            }
        }
    }
#pragma unroll
    for (int i = 0; i < 5; i++)
#pragma unroll
        for (int j = 0; j < 5; j++)
            acc[i][j] += __shfl_xor_sync(0xffffffffu, acc[i][j], 1);
    if (gact && half == 0) {
        float* sp = g_Sp + ((gk*NB + n)*NSP + tile)*625;
#pragma unroll
        for (int i = 0; i < 5; i++)
#pragma unroll
            for (int j = 0; j < 5; j++)
                sp[(vb + i)*25 + wb + j] = acc[i][j];
    }
}

// ---------------- gram finalize: reduce NSP partials + softmax + A -------
__global__ __launch_bounds__(128) void k_gram_final(
    const float* __restrict__ adj, const float* __restrict__ PA)
{
    int n = blockIdx.x, k = blockIdx.y;
    int tid = threadIdx.x;
    __shared__ float Ss[625];
    const float* sp = g_Sp + (k*NB + n)*NSP*625;
    for (int i = tid; i < 625; i += 128) {
        float s = 0.f;
#pragma unroll 6
        for (int p = 0; p < NSP; p++) s += sp[p*625 + i];
        Ss[i] = s * (1.f / 4800.f);
    }
    __syncthreads();
    if (tid < 25) {
        int ww = tid;
        float m = -1e30f;
        for (int vv = 0; vv < 25; vv++) m = fmaxf(m, Ss[vv*25 + ww]);
        float s = 0.f;
        for (int vv = 0; vv < 25; vv++) s += expf(Ss[vv*25 + ww] - m);
        float inv = 1.f / s;
        float* Sp = g_S + (k*NB + n)*625;
        for (int vv = 0; vv < 25; vv++)
            Sp[vv*25 + ww] = expf(Ss[vv*25 + ww] - m)*inv
                           + adj[k*625 + vv*25 + ww] + PA[k*625 + vv*25 + ww];
    }
}

// ===== fused GCN: y1 = sum_k Wd[k] @ (x @ S[k]) + bd  (+BN1 partials) ====
__global__ __launch_bounds__(256, 3) void k_gcn(
    const float* __restrict__ x, const float* __restrict__ bd)
{
    extern __shared__ float sm[];
    float* Xs  = sm;                       // [64][XW]   7936
    float* Zs  = sm + 64*XW;               // [64][AW]   8704
    float* Ssm = sm + 64*XW + 64*AW;       // [3][25][28] 2100
    float* bds = Ssm + 2100;               // [64]
    int tid = threadIdx.x, w8 = tid >> 5, l = tid & 31;
    int tt = blockIdx.x, n = blockIdx.y;
    int p0 = tt * 125;

    for (int i = tid; i < 2100; i += 256) {
        int k = i / 700, r = i % 700;
        int v = r / 28, ww = r % 28;
        Ssm[i] = (ww < 25) ? g_S[(k*NB + n)*625 + v*25 + ww] : 0.f;
    }
    if (tid < 64) bds[tid] = bd[tid] + bd[64 + tid] + bd[128 + tid];
    for (int i = tid; i < 8000; i += 256) {
        int c = i / 125, pl = i % 125;
        Xs[c*XW + pl] = x[(n*64 + c)*TV + p0 + pl];
    }
    __syncthreads();

    float acc[8][4];
#pragma unroll
    for (int nt = 0; nt < 8; nt++)
#pragma unroll
        for (int j = 0; j < 4; j++) acc[nt][j] = 0.f;

    int row = w8*16 + (l >> 2);
    int cq  = l & 3;

#pragma unroll 1
    for (int k = 0; k < 3; k++) {
        const float* Sk = Ssm + k*700;
#pragma unroll 1
        for (int rr = tid; rr < 320; rr += 256) {
            int c = rr / 5, tl = rr % 5;
            const float* xr = Xs + c*XW + tl*25;
            float4 av[7];
#pragma unroll
            for (int q = 0; q < 7; q++) av[q] = make_float4(0.f,0.f,0.f,0.f);
#pragma unroll 5
            for (int v = 0; v < 25; v++) {
                float xv = xr[v];
                const float4* Sv = (const float4*)(Sk + v*28);
#pragma unroll
                for (int q = 0; q < 7; q++) {
                    float4 s4 = Sv[q];
                    av[q].x += xv*s4.x; av[q].y += xv*s4.y;
                    av[q].z += xv*s4.z; av[q].w += xv*s4.w;
                }
            }
            float* zp = Zs + c*AW + tl*25;
            const float* af = (const float*)av;
#pragma unroll
            for (int ww = 0; ww < 25; ww++) zp[ww] = tf32r(af[ww]);
        }
        __syncthreads();
#pragma unroll
        for (int s = 0; s < 8; s++) {
            const float* A0 = Zs + (s*8 + cq)*AW + row;
            uint32_t a0 = __float_as_uint(A0[0]);
            uint32_t a1 = __float_as_uint(A0[8]);
            const float* A2 = A0 + 4*AW;
            uint32_t a2 = __float_as_uint(A2[0]);
            uint32_t a3 = __float_as_uint(A2[8]);
            const float2* B = (const float2*)g_Wdk + (k*8 + s)*8*32 + l;
#pragma unroll
            for (int nt = 0; nt < 8; nt++) {
                float2 b = B[nt*32];
                mma_tf32(acc[nt], a0, a1, a2, a3,
                         __float_as_uint(b.x), __float_as_uint(b.y));
            }
        }
        __syncthreads();
    }
    float* Eout = sm;                      // [64][EW]
#pragma unroll
    for (int nt = 0; nt < 8; nt++) {
        int jl = nt*8 + (l & 3)*2;
        int p  = w8*16 + (l >> 2);
        Eout[jl*EW + p]         = acc[nt][0];
        Eout[(jl+1)*EW + p]     = acc[nt][1];
        Eout[jl*EW + p + 8]     = acc[nt][2];
        Eout[(jl+1)*EW + p + 8] = acc[nt][3];
    }
    __syncthreads();
    for (int i = tid; i < 8000; i += 256) {
        int o = i / 125, pl = i % 125;
        g_y1[(n*64 + o)*TV + p0 + pl] = Eout[o*EW + pl] + bds[o];
    }
    if (tid < 64) {
        float s = 0.f, q = 0.f;
        float bv = bds[tid];
        for (int pl = 0; pl < 125; pl++) {
            float u = Eout[tid*EW + pl] + bv;
            s += u; q += u*u;
        }
        g_pA_s[tid*NPA + n*NTT + tt] = s;
        g_pA_q[tid*NPA + n*NTT + tt] = q;
    }
}

// ---------------- BN finalize from partials -------------------------------
__global__ void k_bn_final(const float* __restrict__ g, const float* __restrict__ b,
                           const float* __restrict__ ps, const float* __restrict__ pq,
                           int npart, int which)
{
    int o = blockIdx.x;
    int tid = threadIdx.x;
    __shared__ float red[256];
    float s = 0.f, s2 = 0.f;
    for (int i = tid; i < npart; i += 128) {
        s  += ps[o*npart + i];
        s2 += pq[o*npart + i];
    }
    red[tid] = s; red[128 + tid] = s2;
    __syncthreads();
    for (int st = 64; st > 0; st >>= 1) {
        if (tid < st) {
            red[tid]       += red[tid + st];
            red[128 + tid] += red[128 + tid + st];
        }
        __syncthreads();
    }
    if (tid == 0) {
        const float cnt = (float)(NB*TV);
        float mean = red[0] / cnt;
        float var  = red[128] / cnt - mean*mean;
        float sc = g[o] * rsqrtf(var + BNEPS);
        g_stat[which*128 + o*2 + 0] = sc;
        g_stat[which*128 + o*2 + 1] = b[o] - mean*sc;
    }
}

// ====== tcn: s outer, kt inner, B from L2 (no smem weights, 1 sync) ======
__global__ __launch_bounds__(512, 1) void k_tcn_mma(
    const float* __restrict__ x, const float* __restrict__ bt)
{
    extern __shared__ float sm[];
    float* Ys  = sm;                    // [64][456]
    float* aux = sm + 64*YW;            // [0..63]=bt, [64..191]=bn1 stats
    int tid = threadIdx.x, w = tid >> 5, l = tid & 31;
    int tile = blockIdx.x, n = blockIdx.y;
    int p0 = tile * TILE_P;

    if (tid < 64)  aux[tid] = bt[tid];
    if (tid < 128) aux[64 + tid] = g_stat[tid];
    __syncthreads();

    for (int i = tid; i < 64*YW; i += 512) {
        int cin = i / YW, pl = i % YW;
        int pg = p0 - 100 + pl;
        float val = 0.f;
        if (pg >= 0 && pg < TV) {
            int idx = (n*64 + cin)*TV + pg;
            val = fmaxf(0.f, g_y1[idx]*aux[64 + cin*2] + aux[64 + cin*2 + 1] + x[idx]);
        }
        Ys[i] = tf32r(val);
    }
    __syncthreads();

    float c[8][4];
#pragma unroll
    for (int nt = 0; nt < 8; nt++)
#pragma unroll
        for (int j = 0; j < 4; j++) c[nt][j] = 0.f;

    int rbase0 = w*16 + (l >> 2);
    int cbase  = l & 3;
#pragma unroll 1
    for (int s = 0; s < 8; s++) {
        const float* Abase = Ys + (s*8 + cbase)*YW + rbase0;
#pragma unroll 3
        for (int kt = 0; kt < 9; kt++) {
            const float* A0 = Abase + kt*25;
            uint32_t a0 = __float_as_uint(A0[0]);
            uint32_t a1 = __float_as_uint(A0[8]);
            const float* A2 = A0 + 4*YW;
            uint32_t a2 = __float_as_uint(A2[0]);
            uint32_t a3 = __float_as_uint(A2[8]);
            const float2* B = (const float2*)g_Wf + (s*9 + kt)*8*32 + l;
#pragma unroll
            for (int nt = 0; nt < 8; nt++) {
                float2 b = B[nt*32];
                mma_tf32(c[nt], a0, a1, a2, a3,
                         __float_as_uint(b.x), __float_as_uint(b.y));
            }
        }
    }
    __syncthreads();
    float* Sout = sm;                   // [64][258]
#pragma unroll
    for (int nt = 0; nt < 8; nt++) {
        int o = nt*8 + (l & 3)*2;
        int p = w*16 + (l >> 2);
        Sout[o*SOW + p]         = c[nt][0] + aux[o];
        Sout[(o+1)*SOW + p]     = c[nt][1] + aux[o+1];
        Sout[o*SOW + p + 8]     = c[nt][2] + aux[o];
        Sout[(o+1)*SOW + p + 8] = c[nt][3] + aux[o+1];
    }
    __syncthreads();
    if (tid < 64) {
        float s = 0.f, q = 0.f;
        int lim = TV - p0; if (lim > TILE_P) lim = TILE_P;
        for (int p = 0; p < lim; p++) {
            float u = Sout[tid*SOW + p];
            s += u; q += u*u;
        }
        int cta = n*NTILE + tile;
        g_pB_s[tid*NCTA_B + cta] = s;
        g_pB_q[tid*NCTA_B + cta] = q;
    }
    for (int i = tid; i < 64*TILE_P; i += 512) {
        int o = i >> 8, p = i & 255;
        if (p0 + p < TV)
            g_y3[(n*64 + o)*TV + p0 + p] = Sout[o*SOW + p];
    }
}

// ---- final: out = relu(bn2(y3) + x), float4 -----------------------------
__global__ __launch_bounds__(256) void k_bn_apply4(
    const float4* __restrict__ x4, float4* __restrict__ out4)
{
    const float4* y4 = (const float4*)g_y3;
    long total = NCTV/4;
    long stride = (long)gridDim.x*256;
    for (long i = (long)blockIdx.x*256 + threadIdx.x; i < total; i += stride) {
        int o = (int)((i / 1875) & 63);
        float sc = g_stat[128 + o*2 + 0];
        float sf = g_stat[128 + o*2 + 1];
        float4 y = y4[i], xx = x4[i], r;
        r.x = fmaxf(0.f, y.x*sc + sf + xx.x);
        r.y = fmaxf(0.f, y.y*sc + sf + xx.y);
        r.z = fmaxf(0.f, y.z*sc + sf + xx.z);
        r.w = fmaxf(0.f, y.w*sc + sf + xx.w);
        out4[i] = r;
    }
}

// ---------------- launch --------------------------------------------------
extern "C" void kernel_launch(void* const* d_in, const int* in_sizes, int n_in,
                              void* d_out, int out_size)
{
    const float* x    = (const float*)d_in[0];
    const float* adj  = (const float*)d_in[1];
    const float* PA   = (const float*)d_in[2];
    const float* Wa   = (const float*)d_in[3];
    const float* ba   = (const float*)d_in[4];
    const float* Wb   = (const float*)d_in[5];
    const float* bb   = (const float*)d_in[6];
    const float* Wd   = (const float*)d_in[7];
    const float* bd   = (const float*)d_in[8];
    const float* g1   = (const float*)d_in[9];
    const float* b1   = (const float*)d_in[10];
    const float* Wt   = (const float*)d_in[11];
    const float* bt   = (const float*)d_in[12];
    const float* g2   = (const float*)d_in[13];
    const float* b2   = (const float*)d_in[14];
    float* out = (float*)d_out;

    float *pAs, *pAq, *pBs, *pBq;
    cudaGetSymbolAddress((void**)&pAs, g_pA_s);
    cudaGetSymbolAddress((void**)&pAq, g_pA_q);
    cudaGetSymbolAddress((void**)&pBs, g_pB_s);
    cudaGetSymbolAddress((void**)&pBq, g_pB_q);

    const int tcn_smem  = (64*YW + 192) * 4;                 // 117504 B
    const int fg_smem   = (12672 + 96) * 4;                  // 51072 B
    const int gcn_smem  = (64*XW + 64*AW + 2100 + 64) * 4;   // 75280 B
    static int smem_set = 0;
    if (!smem_set) {
        cudaFuncSetAttribute(k_tcn_mma,
                             cudaFuncAttributeMaxDynamicSharedMemorySize, tcn_smem);
        cudaFuncSetAttribute(k_fabgram,
                             cudaFuncAttributeMaxDynamicSharedMemorySize, fg_smem);
        cudaFuncSetAttribute(k_gcn,
                             cudaFuncAttributeMaxDynamicSharedMemorySize, gcn_smem);
        smem_set = 1;
    }

    k_prep_wt<<<72, 256>>>(Wt);
    k_prep_wfab<<<12, 256>>>(Wa, Wb);
    k_prep_wd<<<24, 256>>>(Wd);

    k_fabgram<<<dim3(NSP, NB), 256, fg_smem>>>(x, ba, bb);
    k_gram_final<<<dim3(NB, 3), 128>>>(adj, PA);
    k_gcn<<<dim3(NTT, NB), 256, gcn_smem>>>(x, bd);

    k_bn_final<<<64, 128>>>(g1, b1, pAs, pAq, NPA, 0);

    k_tcn_mma<<<dim3(NTILE, NB), 512, tcn_smem>>>(x, bt);

    k_bn_final<<<64, 128>>>(g2, b2, pBs, pBq, NCTA_B, 1);

    k_bn_apply4<<<8192, 256>>>((const float4*)x, (float4*)out);

    // second tuple element: adj_mat passthrough
    long tail = (long)out_size - (long)NCTV;
    if (tail > 0) {
        long cnt = tail < 1875 ? tail : 1875;
        cudaMemcpyAsync(out + NCTV, d_in[1], cnt * sizeof(float),
                        cudaMemcpyDeviceToDevice);
    }
}

// round 14
// speedup vs baseline: 1.2695x; 1.0559x over previous
#include <cuda_runtime.h>
#include <math.h>
#include <stdint.h>

#define NB   64
#define CCH  64
#define TT   300
#define VV   25
#define ICH  16
#define OCH  64
#define KTAP 9
#define TV   (TT*VV)        /* 7500 */
#define CTV  (CCH*TV)       /* 480000 */
#define NCTV (NB*CTV)       /* 30720000 */
#define BNEPS 1e-5f

#define TILE_P 384
#define NTILE  20           /* ceil(7500/384) */
#define NCTA_B (NB*NTILE)   /* 1280 */
#define YW 584              /* tcn halo width: 384+200; 584%32==8 */
#define SOW 386

#define AW 136              /* mma A-tile stride */
#define EW 132              /* epilogue / F stride */

#define XW 130              /* k_gcn x-tile stride */
#define NTT 60              /* gcn t-tiles of 5 */
#define NPA (NB*NTT)        /* 3840 BN1 partials per o */
#define NSP 60              /* gram partials per (k,n) */

__device__ __forceinline__ float tf32r(float v) {
    float o; asm("cvt.rna.tf32.f32 %0, %1;" : "=f"(o) : "f"(v)); return o;
}
__device__ __forceinline__ void mma_tf32(float c[4], uint32_t a0, uint32_t a1,
                                         uint32_t a2, uint32_t a3,
                                         uint32_t b0, uint32_t b1) {
    asm volatile(
        "mma.sync.aligned.m16n8k8.row.col.f32.tf32.tf32.f32 "
        "{%0,%1,%2,%3}, {%4,%5,%6,%7}, {%8,%9}, {%0,%1,%2,%3};"
        : "+f"(c[0]), "+f"(c[1]), "+f"(c[2]), "+f"(c[3])
        : "r"(a0), "r"(a1), "r"(a2), "r"(a3), "r"(b0), "r"(b1));
}

// ---------------- scratch (device globals; no allocation) ----------------
__device__ float g_Sp[3*NB*NSP*625];       // gram partials
__device__ float g_S[3*NB*VV*VV];          // attention matrices
__device__ float g_y1[NB*OCH*TV];          // gcn pre-BN
__device__ float g_y3[NB*OCH*TV];          // tcn output
__device__ float g_Wf[8*9*8*32*2];         // tcn B frags [s][kt][nt][lane][2]
__device__ float g_Wfab[8*12*32*2];        // fab packed B frags
__device__ float g_Wdk[3*8*8*32*2];        // Wd packed B frags per k
__device__ float g_pA_s[OCH*NPA];          // BN1 partials
__device__ float g_pA_q[OCH*NPA];
__device__ float g_pB_s[OCH*NCTA_B];       // BN2 partials
__device__ float g_pB_q[OCH*NCTA_B];
__device__ float g_stat[2*OCH*2];          // [which][o][{scale,shift}]

// ---- Wt -> B frags: [s][kt][nt][lane][2] (kt-inner layout) --------------
__global__ void k_prep_wt(const float* __restrict__ Wt)
{
    int j = blockIdx.x*256 + threadIdx.x;
    if (j >= 8*9*8*32) return;
    int l  = j & 31;
    int nt = (j >> 5) & 7;
    int r  = j >> 8;
    int kt = r % 9, s = r / 9;
    int cin = s*8 + (l & 3);
    int o   = nt*8 + (l >> 2);
    g_Wf[j*2 + 0] = tf32r(Wt[(o*64 + cin)*9 + kt]);
    g_Wf[j*2 + 1] = tf32r(Wt[(o*64 + cin + 4)*9 + kt]);
}

// ---- pack Wa/Wb into fab B frags: [s][nt12][lane][2] --------------------
__global__ void k_prep_wfab(const float* __restrict__ Wa,
                            const float* __restrict__ Wb)
{
    int i = blockIdx.x*256 + threadIdx.x;
    if (i >= 8*12*32) return;
    int l  = i & 31;
    int nt = (i >> 5) % 12;
    int s  = i / (32*12);
    int j  = nt*8 + (l >> 2);
    int c0 = s*8 + (l & 3);
    int k = j >> 5, ch = j & 31;
    const float* W = (ch < 16) ? (Wa + (k*16 + ch)*64) : (Wb + (k*16 + ch - 16)*64);
    g_Wfab[i*2 + 0] = tf32r(W[c0]);
    g_Wfab[i*2 + 1] = tf32r(W[c0 + 4]);
}

// ---- pack Wd into per-k B frags: [k][s][nt][lane][2] --------------------
__global__ void k_prep_wd(const float* __restrict__ Wd)
{
    int i = blockIdx.x*256 + threadIdx.x;
    if (i >= 3*8*8*32) return;
    int l  = i & 31;
    int nt = (i >> 5) & 7;
    int s  = (i >> 8) & 7;
    int k  = i >> 11;
    int cin = s*8 + (l & 3);
    int o   = nt*8 + (l >> 2);
    g_Wdk[i*2 + 0] = tf32r(Wd[(k*64 + o)*64 + cin]);
    g_Wdk[i*2 + 1] = tf32r(Wd[(k*64 + o)*64 + cin + 4]);
}

// ==== fused fa/fb conv + per-tile gram, single-shot, grid 3840, occ 4 ====
__global__ __launch_bounds__(256, 4) void k_fabgram(
    const float* __restrict__ x, const float* __restrict__ ba,
    const float* __restrict__ bb)
{
    extern __shared__ float sm[];
    float* As  = sm;                 // [64][AW] 8704 (phase 1)
    float* E   = sm;                 // [96][EW] 12672 (phase 2, aliases)
    float* bsm = sm + 12672;         // [96]
    int tid = threadIdx.x, w = tid >> 5, l = tid & 31;
    int tile = blockIdx.x, n = blockIdx.y;
    int p0 = tile * 125;

    if (tid < 96) {
        int k = tid >> 5, ch = tid & 31;
        bsm[tid] = (ch < 16) ? ba[k*16 + ch] : bb[k*16 + ch - 16];
    }
    for (int i = tid; i < 64*128; i += 256) {
        int c = i >> 7, p = i & 127;
        As[c*AW + p] = (p < 125) ? tf32r(x[(n*64 + c)*TV + p0 + p]) : 0.f;
    }
    __syncthreads();

    int row = w*16 + (l >> 2);
    int cq  = l & 3;

    float c[12][4];
#pragma unroll
    for (int nt = 0; nt < 12; nt++)
#pragma unroll
        for (int j = 0; j < 4; j++) c[nt][j] = 0.f;
#pragma unroll 1
    for (int s = 0; s < 8; s++) {
        const float* A0 = As + (s*8 + cq)*AW + row;
        uint32_t a0 = __float_as_uint(A0[0]);
        uint32_t a1 = __float_as_uint(A0[8]);
        const float* A2 = A0 + 4*AW;
        uint32_t a2 = __float_as_uint(A2[0]);
        uint32_t a3 = __float_as_uint(A2[8]);
        const float2* B = (const float2*)g_Wfab + s*12*32 + l;
#pragma unroll
        for (int nt = 0; nt < 12; nt++) {
            float2 b = B[nt*32];
            mma_tf32(c[nt], a0, a1, a2, a3,
                     __float_as_uint(b.x), __float_as_uint(b.y));
        }
    }
    __syncthreads();                // As consumed -> reuse as E
#pragma unroll
    for (int nt = 0; nt < 12; nt++) {
        int jl = nt*8 + (l & 3)*2;
        int p  = w*16 + (l >> 2);
        float b0 = bsm[jl], b1 = bsm[jl+1];
        E[jl*EW + p]           = c[nt][0] + b0;
        E[(jl+1)*EW + p]       = c[nt][1] + b1;
        E[jl*EW + p + 8]       = c[nt][2] + b0;
        E[(jl+1)*EW + p + 8]   = c[nt][3] + b1;
    }
    __syncthreads();
    // ---- gram partial over this tile's 5 t-rows, from E in smem
    int u = tid >> 1, half = tid & 1;
    bool gact = u < 75;
    float acc[5][5];
#pragma unroll
    for (int i = 0; i < 5; i++)
#pragma unroll
        for (int j = 0; j < 5; j++) acc[i][j] = 0.f;
    int gk = u / 25, gt = u % 25;
    int vb = (gt / 5) * 5, wb = (gt % 5) * 5;
    if (gact) {
        const float* Fa0 = E + (gk*32)*EW;
        const float* Fb0 = E + (gk*32 + 16)*EW;
#pragma unroll 1
        for (int t = half; t < 5; t += 2) {
#pragma unroll
            for (int o = 0; o < 16; o++) {
                const float* fa = Fa0 + o*EW + t*25 + vb;
                const float* fb = Fb0 + o*EW + t*25 + wb;
                float av[5], bv[5];
#pragma unroll
                for (int i = 0; i < 5; i++) av[i] = fa[i];
#pragma unroll
                for (int j = 0; j < 5; j++) bv[j] = fb[j];
#pragma unroll
                for (int i = 0; i < 5; i++)
#pragma unroll
                    for (int j = 0; j < 5; j++) acc[i][j] += av[i]*bv[j];
            }
        }
    }
#pragma unroll
    for (int i = 0; i < 5; i++)
#pragma unroll
        for (int j = 0; j < 5; j++)
            acc[i][j] += __shfl_xor_sync(0xffffffffu, acc[i][j], 1);
    if (gact && half == 0) {
        float* sp = g_Sp + ((gk*NB + n)*NSP + tile)*625;
#pragma unroll
        for (int i = 0; i < 5; i++)
#pragma unroll
            for (int j = 0; j < 5; j++)
                sp[(vb + i)*25 + wb + j] = acc[i][j];
    }
}

// ---------------- gram finalize: reduce NSP partials + softmax + A -------
__global__ __launch_bounds__(128) void k_gram_final(
    const float* __restrict__ adj, const float* __restrict__ PA)
{
    int n = blockIdx.x, k = blockIdx.y;
    int tid = threadIdx.x;
    __shared__ float Ss[625];
    const float* sp = g_Sp + (k*NB + n)*NSP*625;
    for (int i = tid; i < 625; i += 128) {
        float s = 0.f;
#pragma unroll 6
        for (int p = 0; p < NSP; p++) s += sp[p*625 + i];
        Ss[i] = s * (1.f / 4800.f);
    }
    __syncthreads();
    if (tid < 25) {
        int ww = tid;
        float m = -1e30f;
        for (int vv = 0; vv < 25; vv++) m = fmaxf(m, Ss[vv*25 + ww]);
        float s = 0.f;
        for (int vv = 0; vv < 25; vv++) s += expf(Ss[vv*25 + ww] - m);
        float inv = 1.f / s;
        float* Sp = g_S + (k*NB + n)*625;
        for (int vv = 0; vv < 25; vv++)
            Sp[vv*25 + ww] = expf(Ss[vv*25 + ww] - m)*inv
                           + adj[k*625 + vv*25 + ww] + PA[k*625 + vv*25 + ww];
    }
}

// ===== fused GCN: y1 = sum_k Wd[k] @ (x @ S[k]) + bd  (+BN1 partials) ====
__global__ __launch_bounds__(256) void k_gcn(
    const float* __restrict__ x, const float* __restrict__ bd)
{
    extern __shared__ float sm[];
    float* Xs  = sm;                       // [64][XW]   8320
    float* Zs  = sm + 64*XW;               // [64][AW]   8704
    float* Ssm = sm + 64*XW + 64*AW;       // [3][25][28] 2100
    float* bds = Ssm + 2100;               // [64]
    int tid = threadIdx.x, w8 = tid >> 5, l = tid & 31;
    int tt = blockIdx.x, n = blockIdx.y;
    int p0 = tt * 125;

    for (int i = tid; i < 2100; i += 256) {
        int k = i / 700, r = i % 700;
        int v = r / 28, ww = r % 28;
        Ssm[i] = (ww < 25) ? g_S[(k*NB + n)*625 + v*25 + ww] : 0.f;
    }
    if (tid < 64) bds[tid] = bd[tid] + bd[64 + tid] + bd[128 + tid];
    for (int i = tid; i < 8000; i += 256) {
        int c = i / 125, pl = i % 125;
        Xs[c*XW + pl] = x[(n*64 + c)*TV + p0 + pl];
    }
    __syncthreads();

    float acc[8][4];
#pragma unroll
    for (int nt = 0; nt < 8; nt++)
#pragma unroll
        for (int j = 0; j < 4; j++) acc[nt][j] = 0.f;

    int row = w8*16 + (l >> 2);
    int cq  = l & 3;

#pragma unroll 1
    for (int k = 0; k < 3; k++) {
        const float* Sk = Ssm + k*700;
#pragma unroll 1
        for (int rr = tid; rr < 320; rr += 256) {
            int c = rr / 5, tl = rr % 5;
            const float* xr = Xs + c*XW + tl*25;
            float4 av[7];
#pragma unroll
            for (int q = 0; q < 7; q++) av[q] = make_float4(0.f,0.f,0.f,0.f);
#pragma unroll 5
            for (int v = 0; v < 25; v++) {
                float xv = xr[v];
                const float4* Sv = (const float4*)(Sk + v*28);
#pragma unroll
                for (int q = 0; q < 7; q++) {
                    float4 s4 = Sv[q];
                    av[q].x += xv*s4.x; av[q].y += xv*s4.y;
                    av[q].z += xv*s4.z; av[q].w += xv*s4.w;
                }
            }
            float* zp = Zs + c*AW + tl*25;
            const float* af = (const float*)av;
#pragma unroll
            for (int ww = 0; ww < 25; ww++) zp[ww] = tf32r(af[ww]);
        }
        __syncthreads();
#pragma unroll
        for (int s = 0; s < 8; s++) {
            const float* A0 = Zs + (s*8 + cq)*AW + row;
            uint32_t a0 = __float_as_uint(A0[0]);
            uint32_t a1 = __float_as_uint(A0[8]);
            const float* A2 = A0 + 4*AW;
            uint32_t a2 = __float_as_uint(A2[0]);
            uint32_t a3 = __float_as_uint(A2[8]);
            const float2* B = (const float2*)g_Wdk + (k*8 + s)*8*32 + l;
#pragma unroll
            for (int nt = 0; nt < 8; nt++) {
                float2 b = B[nt*32];
                mma_tf32(acc[nt], a0, a1, a2, a3,
                         __float_as_uint(b.x), __float_as_uint(b.y));
            }
        }
        __syncthreads();
    }
    float* Eout = sm;                      // [64][EW]
#pragma unroll
    for (int nt = 0; nt < 8; nt++) {
        int jl = nt*8 + (l & 3)*2;
        int p  = w8*16 + (l >> 2);
        Eout[jl*EW + p]         = acc[nt][0];
        Eout[(jl+1)*EW + p]     = acc[nt][1];
        Eout[jl*EW + p + 8]     = acc[nt][2];
        Eout[(jl+1)*EW + p + 8] = acc[nt][3];
    }
    __syncthreads();
    for (int i = tid; i < 8000; i += 256) {
        int o = i / 125, pl = i % 125;
        g_y1[(n*64 + o)*TV + p0 + pl] = Eout[o*EW + pl] + bds[o];
    }
    if (tid < 64) {
        float s = 0.f, q = 0.f;
        float bv = bds[tid];
        for (int pl = 0; pl < 125; pl++) {
            float u = Eout[tid*EW + pl] + bv;
            s += u; q += u*u;
        }
        g_pA_s[tid*NPA + n*NTT + tt] = s;
        g_pA_q[tid*NPA + n*NTT + tt] = q;
    }
}

// ---------------- BN finalize from partials -------------------------------
__global__ void k_bn_final(const float* __restrict__ g, const float* __restrict__ b,
                           const float* __restrict__ ps, const float* __restrict__ pq,
                           int npart, int which)
{
    int o = blockIdx.x;
    int tid = threadIdx.x;
    __shared__ float red[256];
    float s = 0.f, s2 = 0.f;
    for (int i = tid; i < npart; i += 128) {
        s  += ps[o*npart + i];
        s2 += pq[o*npart + i];
    }
    red[tid] = s; red[128 + tid] = s2;
    __syncthreads();
    for (int st = 64; st > 0; st >>= 1) {
        if (tid < st) {
            red[tid]       += red[tid + st];
            red[128 + tid] += red[128 + tid + st];
        }
        __syncthreads();
    }
    if (tid == 0) {
        const float cnt = (float)(NB*TV);
        float mean = red[0] / cnt;
        float var  = red[128] / cnt - mean*mean;
        float sc = g[o] * rsqrtf(var + BNEPS);
        g_stat[which*128 + o*2 + 0] = sc;
        g_stat[which*128 + o*2 + 1] = b[o] - mean*sc;
    }
}

// ====== tcn: TILE_P=384, 768 thr, s outer, kt inner, B from L2 ===========
__global__ __launch_bounds__(768, 1) void k_tcn_mma(
    const float* __restrict__ x, const float* __restrict__ bt)
{
    extern __shared__ float sm[];
    float* Ys  = sm;                    // [64][584]
    float* aux = sm + 64*YW;            // [0..63]=bt, [64..191]=bn1 stats
    int tid = threadIdx.x, w = tid >> 5, l = tid & 31;
    int tile = blockIdx.x, n = blockIdx.y;
    int p0 = tile * TILE_P;

    if (tid < 64)  aux[tid] = bt[tid];
    if (tid < 128) aux[64 + tid] = g_stat[tid];
    __syncthreads();

    for (int i = tid; i < 64*YW; i += 768) {
        int cin = i / YW, pl = i % YW;
        int pg = p0 - 100 + pl;
        float val = 0.f;
        if (pg >= 0 && pg < TV) {
            int idx = (n*64 + cin)*TV + pg;
            val = fmaxf(0.f, g_y1[idx]*aux[64 + cin*2] + aux[64 + cin*2 + 1] + x[idx]);
        }
        Ys[i] = tf32r(val);
    }
    __syncthreads();

    float c[8][4];
#pragma unroll
    for (int nt = 0; nt < 8; nt++)
#pragma unroll
        for (int j = 0; j < 4; j++) c[nt][j] = 0.f;

    int rbase0 = w*16 + (l >> 2);       // w 0..23 -> rows 0..383
    int cbase  = l & 3;
#pragma unroll 1
    for (int s = 0; s < 8; s++) {
        const float* Abase = Ys + (s*8 + cbase)*YW + rbase0;
#pragma unroll 3
        for (int kt = 0; kt < 9; kt++) {
            const float* A0 = Abase + kt*25;
            uint32_t a0 = __float_as_uint(A0[0]);
            uint32_t a1 = __float_as_uint(A0[8]);
            const float* A2 = A0 + 4*YW;
            uint32_t a2 = __float_as_uint(A2[0]);
            uint32_t a3 = __float_as_uint(A2[8]);
            const float2* B = (const float2*)g_Wf + (s*9 + kt)*8*32 + l;
#pragma unroll
            for (int nt = 0; nt < 8; nt++) {
                float2 b = B[nt*32];
                mma_tf32(c[nt], a0, a1, a2, a3,
                         __float_as_uint(b.x), __float_as_uint(b.y));
            }
        }
    }
    __syncthreads();
    float* Sout = sm;                   // [64][386]
#pragma unroll
    for (int nt = 0; nt < 8; nt++) {
        int o = nt*8 + (l & 3)*2;
        int p = w*16 + (l >> 2);
        Sout[o*SOW + p]         = c[nt][0] + aux[o];
        Sout[(o+1)*SOW + p]     = c[nt][1] + aux[o+1];
        Sout[o*SOW + p + 8]     = c[nt][2] + aux[o];
        Sout[(o+1)*SOW + p + 8] = c[nt][3] + aux[o+1];
    }
    __syncthreads();
    if (tid < 64) {
        float s = 0.f, q = 0.f;
        int lim = TV - p0; if (lim > TILE_P) lim = TILE_P;
        for (int p = 0; p < lim; p++) {
            float u = Sout[tid*SOW + p];
            s += u; q += u*u;
        }
        int cta = n*NTILE + tile;
        g_pB_s[tid*NCTA_B + cta] = s;
        g_pB_q[tid*NCTA_B + cta] = q;
    }
    for (int i = tid; i < 64*TILE_P; i += 768) {
        int o = i / TILE_P, p = i % TILE_P;
        if (p0 + p < TV)
            g_y3[(n*64 + o)*TV + p0 + p] = Sout[o*SOW + p];
    }
}

// ---- final: out = relu(bn2(y3) + x), float4 -----------------------------
__global__ __launch_bounds__(256) void k_bn_apply4(
    const float4* __restrict__ x4, float4* __restrict__ out4)
{
    const float4* y4 = (const float4*)g_y3;
    long total = NCTV/4;
    long stride = (long)gridDim.x*256;
    for (long i = (long)blockIdx.x*256 + threadIdx.x; i < total; i += stride) {
        int o = (int)((i / 1875) & 63);
        float sc = g_stat[128 + o*2 + 0];
        float sf = g_stat[128 + o*2 + 1];
        float4 y = y4[i], xx = x4[i], r;
        r.x = fmaxf(0.f, y.x*sc + sf + xx.x);
        r.y = fmaxf(0.f, y.y*sc + sf + xx.y);
        r.z = fmaxf(0.f, y.z*sc + sf + xx.z);
        r.w = fmaxf(0.f, y.w*sc + sf + xx.w);
        out4[i] = r;
    }
}

// ---------------- launch --------------------------------------------------
extern "C" void kernel_launch(void* const* d_in, const int* in_sizes, int n_in,
                              void* d_out, int out_size)
{
    const float* x    = (const float*)d_in[0];
    const float* adj  = (const float*)d_in[1];
    const float* PA   = (const float*)d_in[2];
    const float* Wa   = (const float*)d_in[3];
    const float* ba   = (const float*)d_in[4];
    const float* Wb   = (const float*)d_in[5];
    const float* bb   = (const float*)d_in[6];
    const float* Wd   = (const float*)d_in[7];
    const float* bd   = (const float*)d_in[8];
    const float* g1   = (const float*)d_in[9];
    const float* b1   = (const float*)d_in[10];
    const float* Wt   = (const float*)d_in[11];
    const float* bt   = (const float*)d_in[12];
    const float* g2   = (const float*)d_in[13];
    const float* b2   = (const float*)d_in[14];
    float* out = (float*)d_out;

    float *pAs, *pAq, *pBs, *pBq;
    cudaGetSymbolAddress((void**)&pAs, g_pA_s);
    cudaGetSymbolAddress((void**)&pAq, g_pA_q);
    cudaGetSymbolAddress((void**)&pBs, g_pB_s);
    cudaGetSymbolAddress((void**)&pBq, g_pB_q);

    const int tcn_smem  = (64*YW + 192) * 4;                 // 150272 B
    const int fg_smem   = (12672 + 96) * 4;                  // 51072 B
    const int gcn_smem  = (64*XW + 64*AW + 2100 + 64) * 4;   // 76752 B
    static int smem_set = 0;
    if (!smem_set) {
        cudaFuncSetAttribute(k_tcn_mma,
                             cudaFuncAttributeMaxDynamicSharedMemorySize, tcn_smem);
        cudaFuncSetAttribute(k_fabgram,
                             cudaFuncAttributeMaxDynamicSharedMemorySize, fg_smem);
        cudaFuncSetAttribute(k_gcn,
                             cudaFuncAttributeMaxDynamicSharedMemorySize, gcn_smem);
        smem_set = 1;
    }

    k_prep_wt<<<72, 256>>>(Wt);
    k_prep_wfab<<<12, 256>>>(Wa, Wb);
    k_prep_wd<<<24, 256>>>(Wd);

    k_fabgram<<<dim3(NSP, NB), 256, fg_smem>>>(x, ba, bb);
    k_gram_final<<<dim3(NB, 3), 128>>>(adj, PA);
    k_gcn<<<dim3(NTT, NB), 256, gcn_smem>>>(x, bd);

    k_bn_final<<<64, 128>>>(g1, b1, pAs, pAq, NPA, 0);

    k_tcn_mma<<<dim3(NTILE, NB), 768, tcn_smem>>>(x, bt);

    k_bn_final<<<64, 128>>>(g2, b2, pBs, pBq, NCTA_B, 1);

    k_bn_apply4<<<8192, 256>>>((const float4*)x, (float4*)out);

    // second tuple element: adj_mat passthrough
    long tail = (long)out_size - (long)NCTV;
    if (tail > 0) {
        long cnt = tail < 1875 ? tail : 1875;
        cudaMemcpyAsync(out + NCTV, d_in[1], cnt * sizeof(float),
                        cudaMemcpyDeviceToDevice);
    }
}

// round 15
// speedup vs baseline: 1.2965x; 1.0213x over previous
#include <cuda_runtime.h>
#include <cuda_bf16.h>
#include <math.h>
#include <stdint.h>

#define NB   64
#define CCH  64
#define TT   300
#define VV   25
#define ICH  16
#define OCH  64
#define KTAP 9
#define TV   (TT*VV)        /* 7500 */
#define CTV  (CCH*TV)       /* 480000 */
#define NCTV (NB*CTV)       /* 30720000 */
#define BNEPS 1e-5f

#define TILE_P 384
#define NTILE  20           /* ceil(7500/384) */
#define NCTA_B (NB*NTILE)   /* 1280 */
#define YW 584              /* tcn halo width: 384+200; 584%32==8 */
#define SOW 386

#define AW 136              /* mma A-tile stride */
#define EW 132              /* epilogue / F stride */

#define XW 130              /* k_gcn x-tile stride */
#define NTT 60              /* gcn t-tiles of 5 */
#define NPA (NB*NTT)        /* 3840 BN1 partials per o */
#define NSP 60              /* gram partials per (k,n) */

__device__ __forceinline__ float tf32r(float v) {
    float o; asm("cvt.rna.tf32.f32 %0, %1;" : "=f"(o) : "f"(v)); return o;
}
__device__ __forceinline__ void mma_tf32(float c[4], uint32_t a0, uint32_t a1,
                                         uint32_t a2, uint32_t a3,
                                         uint32_t b0, uint32_t b1) {
    asm volatile(
        "mma.sync.aligned.m16n8k8.row.col.f32.tf32.tf32.f32 "
        "{%0,%1,%2,%3}, {%4,%5,%6,%7}, {%8,%9}, {%0,%1,%2,%3};"
        : "+f"(c[0]), "+f"(c[1]), "+f"(c[2]), "+f"(c[3])
        : "r"(a0), "r"(a1), "r"(a2), "r"(a3), "r"(b0), "r"(b1));
}

// ---------------- scratch (device globals; no allocation) ----------------
__device__ float g_Sp[3*NB*NSP*625];       // gram partials
__device__ float g_S[3*NB*VV*VV];          // attention matrices
__device__ __nv_bfloat16 g_y1b[NB*OCH*TV]; // gcn pre-BN (bf16 storage)
__device__ float g_y3[NB*OCH*TV];          // tcn output
__device__ float g_Wf[8*9*8*32*2];         // tcn B frags [s][kt][nt][lane][2]
__device__ float g_Wfab[8*12*32*2];        // fab packed B frags
__device__ float g_Wdk[3*8*8*32*2];        // Wd packed B frags per k
__device__ float g_pA_s[OCH*NPA];          // BN1 partials
__device__ float g_pA_q[OCH*NPA];
__device__ float g_pB_s[OCH*NCTA_B];       // BN2 partials
__device__ float g_pB_q[OCH*NCTA_B];
__device__ float g_stat[2*OCH*2];          // [which][o][{scale,shift}]

// ---- Wt -> B frags: [s][kt][nt][lane][2] (kt-inner layout) --------------
__global__ void k_prep_wt(const float* __restrict__ Wt)
{
    int j = blockIdx.x*256 + threadIdx.x;
    if (j >= 8*9*8*32) return;
    int l  = j & 31;
    int nt = (j >> 5) & 7;
    int r  = j >> 8;
    int kt = r % 9, s = r / 9;
    int cin = s*8 + (l & 3);
    int o   = nt*8 + (l >> 2);
    g_Wf[j*2 + 0] = tf32r(Wt[(o*64 + cin)*9 + kt]);
    g_Wf[j*2 + 1] = tf32r(Wt[(o*64 + cin + 4)*9 + kt]);
}

// ---- pack Wa/Wb into fab B frags: [s][nt12][lane][2] --------------------
__global__ void k_prep_wfab(const float* __restrict__ Wa,
                            const float* __restrict__ Wb)
{
    int i = blockIdx.x*256 + threadIdx.x;
    if (i >= 8*12*32) return;
    int l  = i & 31;
    int nt = (i >> 5) % 12;
    int s  = i / (32*12);
    int j  = nt*8 + (l >> 2);
    int c0 = s*8 + (l & 3);
    int k = j >> 5, ch = j & 31;
    const float* W = (ch < 16) ? (Wa + (k*16 + ch)*64) : (Wb + (k*16 + ch - 16)*64);
    g_Wfab[i*2 + 0] = tf32r(W[c0]);
    g_Wfab[i*2 + 1] = tf32r(W[c0 + 4]);
}

// ---- pack Wd into per-k B frags: [k][s][nt][lane][2] --------------------
__global__ void k_prep_wd(const float* __restrict__ Wd)
{
    int i = blockIdx.x*256 + threadIdx.x;
    if (i >= 3*8*8*32) return;
    int l  = i & 31;
    int nt = (i >> 5) & 7;
    int s  = (i >> 8) & 7;
    int k  = i >> 11;
    int cin = s*8 + (l & 3);
    int o   = nt*8 + (l >> 2);
    g_Wdk[i*2 + 0] = tf32r(Wd[(k*64 + o)*64 + cin]);
    g_Wdk[i*2 + 1] = tf32r(Wd[(k*64 + o)*64 + cin + 4]);
}

// ==== fused fa/fb conv + per-tile gram, single-shot, grid 3840, occ 4 ====
__global__ __launch_bounds__(256, 4) void k_fabgram(
    const float* __restrict__ x, const float* __restrict__ ba,
    const float* __restrict__ bb)
{
    extern __shared__ float sm[];
    float* As  = sm;                 // [64][AW] 8704 (phase 1)
    float* E   = sm;                 // [96][EW] 12672 (phase 2, aliases)
    float* bsm = sm + 12672;         // [96]
    int tid = threadIdx.x, w = tid >> 5, l = tid & 31;
    int tile = blockIdx.x, n = blockIdx.y;
    int p0 = tile * 125;

    if (tid < 96) {
        int k = tid >> 5, ch = tid & 31;
        bsm[tid] = (ch < 16) ? ba[k*16 + ch] : bb[k*16 + ch - 16];
    }
    for (int i = tid; i < 64*128; i += 256) {
        int c = i >> 7, p = i & 127;
        As[c*AW + p] = (p < 125) ? tf32r(x[(n*64 + c)*TV + p0 + p]) : 0.f;
    }
    __syncthreads();

    int row = w*16 + (l >> 2);
    int cq  = l & 3;

    float c[12][4];
#pragma unroll
    for (int nt = 0; nt < 12; nt++)
#pragma unroll
        for (int j = 0; j < 4; j++) c[nt][j] = 0.f;
#pragma unroll 1
    for (int s = 0; s < 8; s++) {
        const float* A0 = As + (s*8 + cq)*AW + row;
        uint32_t a0 = __float_as_uint(A0[0]);
        uint32_t a1 = __float_as_uint(A0[8]);
        const float* A2 = A0 + 4*AW;
        uint32_t a2 = __float_as_uint(A2[0]);
        uint32_t a3 = __float_as_uint(A2[8]);
        const float2* B = (const float2*)g_Wfab + s*12*32 + l;
#pragma unroll
        for (int nt = 0; nt < 12; nt++) {
            float2 b = B[nt*32];
            mma_tf32(c[nt], a0, a1, a2, a3,
                     __float_as_uint(b.x), __float_as_uint(b.y));
        }
    }
    __syncthreads();                // As consumed -> reuse as E
#pragma unroll
    for (int nt = 0; nt < 12; nt++) {
        int jl = nt*8 + (l & 3)*2;
        int p  = w*16 + (l >> 2);
        float b0 = bsm[jl], b1 = bsm[jl+1];
        E[jl*EW + p]           = c[nt][0] + b0;
        E[(jl+1)*EW + p]       = c[nt][1] + b1;
        E[jl*EW + p + 8]       = c[nt][2] + b0;
        E[(jl+1)*EW + p + 8]   = c[nt][3] + b1;
    }
    __syncthreads();
    // ---- gram partial over this tile's 5 t-rows, from E in smem
    int u = tid >> 1, half = tid & 1;
    bool gact = u < 75;
    float acc[5][5];
#pragma unroll
    for (int i = 0; i < 5; i++)
#pragma unroll
        for (int j = 0; j < 5; j++) acc[i][j] = 0.f;
    int gk = u / 25, gt = u % 25;
    int vb = (gt / 5) * 5, wb = (gt % 5) * 5;
    if (gact) {
        const float* Fa0 = E + (gk*32)*EW;
        const float* Fb0 = E + (gk*32 + 16)*EW;
#pragma unroll 1
        for (int t = half; t < 5; t += 2) {
#pragma unroll
            for (int o = 0; o < 16; o++) {
                const float* fa = Fa0 + o*EW + t*25 + vb;
                const float* fb = Fb0 + o*EW + t*25 + wb;
                float av[5], bv[5];
#pragma unroll
                for (int i = 0; i < 5; i++) av[i] = fa[i];
#pragma unroll
                for (int j = 0; j < 5; j++) bv[j] = fb[j];
#pragma unroll
                for (int i = 0; i < 5; i++)
#pragma unroll
                    for (int j = 0; j < 5; j++) acc[i][j] += av[i]*bv[j];
            }
        }
    }
#pragma unroll
    for (int i = 0; i < 5; i++)
#pragma unroll
        for (int j = 0; j < 5; j++)
            acc[i][j] += __shfl_xor_sync(0xffffffffu, acc[i][j], 1);
    if (gact && half == 0) {
        float* sp = g_Sp + ((gk*NB + n)*NSP + tile)*625;
#pragma unroll
        for (int i = 0; i < 5; i++)
#pragma unroll
            for (int j = 0; j < 5; j++)
                sp[(vb + i)*25 + wb + j] = acc[i][j];
    }
}

// ---------------- gram finalize: reduce NSP partials + softmax + A -------
__global__ __launch_bounds__(128) void k_gram_final(
    const float* __restrict__ adj, const float* __restrict__ PA)
{
    int n = blockIdx.x, k = blockIdx.y;
    int tid = threadIdx.x;
    __shared__ float Ss[625];
    const float* sp = g_Sp + (k*NB + n)*NSP*625;
    for (int i = tid; i < 625; i += 128) {
        float s = 0.f;
#pragma unroll 6
        for (int p = 0; p < NSP; p++) s += sp[p*625 + i];
        Ss[i] = s * (1.f / 4800.f);
    }
    __syncthreads();
    if (tid < 25) {
        int ww = tid;
        float m = -1e30f;
        for (int vv = 0; vv < 25; vv++) m = fmaxf(m, Ss[vv*25 + ww]);
        float s = 0.f;
        for (int vv = 0; vv < 25; vv++) s += expf(Ss[vv*25 + ww] - m);
        float inv = 1.f / s;
        float* Sp = g_S + (k*NB + n)*625;
        for (int vv = 0; vv < 25; vv++)
            Sp[vv*25 + ww] = expf(Ss[vv*25 + ww] - m)*inv
                           + adj[k*625 + vv*25 + ww] + PA[k*625 + vv*25 + ww];
    }
}

// ===== fused GCN: y1 = sum_k Wd[k] @ (x @ S[k]) + bd  (+BN1 partials) ====
__global__ __launch_bounds__(256) void k_gcn(
    const float* __restrict__ x, const float* __restrict__ bd)
{
    extern __shared__ float sm[];
    float* Xs  = sm;                       // [64][XW]   8320
    float* Zs  = sm + 64*XW;               // [64][AW]   8704
    float* Ssm = sm + 64*XW + 64*AW;       // [3][25][28] 2100
    float* bds = Ssm + 2100;               // [64]
    int tid = threadIdx.x, w8 = tid >> 5, l = tid & 31;
    int tt = blockIdx.x, n = blockIdx.y;
    int p0 = tt * 125;

    for (int i = tid; i < 2100; i += 256) {
        int k = i / 700, r = i % 700;
        int v = r / 28, ww = r % 28;
        Ssm[i] = (ww < 25) ? g_S[(k*NB + n)*625 + v*25 + ww] : 0.f;
    }
    if (tid < 64) bds[tid] = bd[tid] + bd[64 + tid] + bd[128 + tid];
    for (int i = tid; i < 8000; i += 256) {
        int c = i / 125, pl = i % 125;
        Xs[c*XW + pl] = x[(n*64 + c)*TV + p0 + pl];
    }
    __syncthreads();

    float acc[8][4];
#pragma unroll
    for (int nt = 0; nt < 8; nt++)
#pragma unroll
        for (int j = 0; j < 4; j++) acc[nt][j] = 0.f;

    int row = w8*16 + (l >> 2);
    int cq  = l & 3;

#pragma unroll 1
    for (int k = 0; k < 3; k++) {
        const float* Sk = Ssm + k*700;
#pragma unroll 1
        for (int rr = tid; rr < 320; rr += 256) {
            int c = rr / 5, tl = rr % 5;
            const float* xr = Xs + c*XW + tl*25;
            float4 av[7];
#pragma unroll
            for (int q = 0; q < 7; q++) av[q] = make_float4(0.f,0.f,0.f,0.f);
#pragma unroll 5
            for (int v = 0; v < 25; v++) {
                float xv = xr[v];
                const float4* Sv = (const float4*)(Sk + v*28);
#pragma unroll
                for (int q = 0; q < 7; q++) {
                    float4 s4 = Sv[q];
                    av[q].x += xv*s4.x; av[q].y += xv*s4.y;
                    av[q].z += xv*s4.z; av[q].w += xv*s4.w;
                }
            }
            float* zp = Zs + c*AW + tl*25;
            const float* af = (const float*)av;
#pragma unroll
            for (int ww = 0; ww < 25; ww++) zp[ww] = tf32r(af[ww]);
        }
        __syncthreads();
#pragma unroll
        for (int s = 0; s < 8; s++) {
            const float* A0 = Zs + (s*8 + cq)*AW + row;
            uint32_t a0 = __float_as_uint(A0[0]);
            uint32_t a1 = __float_as_uint(A0[8]);
            const float* A2 = A0 + 4*AW;
            uint32_t a2 = __float_as_uint(A2[0]);
            uint32_t a3 = __float_as_uint(A2[8]);
            const float2* B = (const float2*)g_Wdk + (k*8 + s)*8*32 + l;
#pragma unroll
            for (int nt = 0; nt < 8; nt++) {
                float2 b = B[nt*32];
                mma_tf32(acc[nt], a0, a1, a2, a3,
                         __float_as_uint(b.x), __float_as_uint(b.y));
            }
        }
        __syncthreads();
    }
    float* Eout = sm;                      // [64][EW]
#pragma unroll
    for (int nt = 0; nt < 8; nt++) {
        int jl = nt*8 + (l & 3)*2;
        int p  = w8*16 + (l >> 2);
        Eout[jl*EW + p]         = acc[nt][0];
        Eout[(jl+1)*EW + p]     = acc[nt][1];
        Eout[jl*EW + p + 8]     = acc[nt][2];
        Eout[(jl+1)*EW + p + 8] = acc[nt][3];
    }
    __syncthreads();
    for (int i = tid; i < 8000; i += 256) {
        int o = i / 125, pl = i % 125;
        g_y1b[(n*64 + o)*TV + p0 + pl] = __float2bfloat16(Eout[o*EW + pl] + bds[o]);
    }
    if (tid < 64) {
        float s = 0.f, q = 0.f;
        float bv = bds[tid];
        for (int pl = 0; pl < 125; pl++) {
            float u = Eout[tid*EW + pl] + bv;
            s += u; q += u*u;
        }
        g_pA_s[tid*NPA + n*NTT + tt] = s;
        g_pA_q[tid*NPA + n*NTT + tt] = q;
    }
}

// ---------------- BN finalize from partials -------------------------------
__global__ void k_bn_final(const float* __restrict__ g, const float* __restrict__ b,
                           const float* __restrict__ ps, const float* __restrict__ pq,
                           int npart, int which)
{
    int o = blockIdx.x;
    int tid = threadIdx.x;
    __shared__ float red[256];
    float s = 0.f, s2 = 0.f;
    for (int i = tid; i < npart; i += 128) {
        s  += ps[o*npart + i];
        s2 += pq[o*npart + i];
    }
    red[tid] = s; red[128 + tid] = s2;
    __syncthreads();
    for (int st = 64; st > 0; st >>= 1) {
        if (tid < st) {
            red[tid]       += red[tid + st];
            red[128 + tid] += red[128 + tid + st];
        }
        __syncthreads();
    }
    if (tid == 0) {
        const float cnt = (float)(NB*TV);
        float mean = red[0] / cnt;
        float var  = red[128] / cnt - mean*mean;
        float sc = g[o] * rsqrtf(var + BNEPS);
        g_stat[which*128 + o*2 + 0] = sc;
        g_stat[which*128 + o*2 + 1] = b[o] - mean*sc;
    }
}

// ====== tcn: TILE_P=384, 768 thr, y1 from bf16, B from L2 ================
__global__ __launch_bounds__(768, 1) void k_tcn_mma(
    const float* __restrict__ x, const float* __restrict__ bt)
{
    extern __shared__ float sm[];
    float* Ys  = sm;                    // [64][584]
    float* aux = sm + 64*YW;            // [0..63]=bt, [64..191]=bn1 stats
    int tid = threadIdx.x, w = tid >> 5, l = tid & 31;
    int tile = blockIdx.x, n = blockIdx.y;
    int p0 = tile * TILE_P;

    if (tid < 64)  aux[tid] = bt[tid];
    if (tid < 128) aux[64 + tid] = g_stat[tid];
    __syncthreads();

    for (int i = tid; i < 64*YW; i += 768) {
        int cin = i / YW, pl = i % YW;
        int pg = p0 - 100 + pl;
        float val = 0.f;
        if (pg >= 0 && pg < TV) {
            int idx = (n*64 + cin)*TV + pg;
            float y1v = __bfloat162float(g_y1b[idx]);
            val = fmaxf(0.f, y1v*aux[64 + cin*2] + aux[64 + cin*2 + 1] + x[idx]);
        }
        Ys[i] = tf32r(val);
    }
    __syncthreads();

    float c[8][4];
#pragma unroll
    for (int nt = 0; nt < 8; nt++)
#pragma unroll
        for (int j = 0; j < 4; j++) c[nt][j] = 0.f;

    int rbase0 = w*16 + (l >> 2);       // w 0..23 -> rows 0..383
    int cbase  = l & 3;
#pragma unroll 1
    for (int s = 0; s < 8; s++) {
        const float* Abase = Ys + (s*8 + cbase)*YW + rbase0;
#pragma unroll 3
        for (int kt = 0; kt < 9; kt++) {
            const float* A0 = Abase + kt*25;
            uint32_t a0 = __float_as_uint(A0[0]);
            uint32_t a1 = __float_as_uint(A0[8]);
            const float* A2 = A0 + 4*YW;
            uint32_t a2 = __float_as_uint(A2[0]);
            uint32_t a3 = __float_as_uint(A2[8]);
            const float2* B = (const float2*)g_Wf + (s*9 + kt)*8*32 + l;
#pragma unroll
            for (int nt = 0; nt < 8; nt++) {
                float2 b = B[nt*32];
                mma_tf32(c[nt], a0, a1, a2, a3,
                         __float_as_uint(b.x), __float_as_uint(b.y));
            }
        }
    }
    __syncthreads();
    float* Sout = sm;                   // [64][386]
#pragma unroll
    for (int nt = 0; nt < 8; nt++) {
        int o = nt*8 + (l & 3)*2;
        int p = w*16 + (l >> 2);
        Sout[o*SOW + p]         = c[nt][0] + aux[o];
        Sout[(o+1)*SOW + p]     = c[nt][1] + aux[o+1];
        Sout[o*SOW + p + 8]     = c[nt][2] + aux[o];
        Sout[(o+1)*SOW + p + 8] = c[nt][3] + aux[o+1];
    }
    __syncthreads();
    if (tid < 64) {
        float s = 0.f, q = 0.f;
        int lim = TV - p0; if (lim > TILE_P) lim = TILE_P;
        for (int p = 0; p < lim; p++) {
            float u = Sout[tid*SOW + p];
            s += u; q += u*u;
        }
        int cta = n*NTILE + tile;
        g_pB_s[tid*NCTA_B + cta] = s;
        g_pB_q[tid*NCTA_B + cta] = q;
    }
    for (int i = tid; i < 64*TILE_P; i += 768) {
        int o = i / TILE_P, p = i % TILE_P;
        if (p0 + p < TV)
            g_y3[(n*64 + o)*TV + p0 + p] = Sout[o*SOW + p];
    }
}

// ---- final: out = relu(bn2(y3) + x), float4 -----------------------------
__global__ __launch_bounds__(256) void k_bn_apply4(
    const float4* __restrict__ x4, float4* __restrict__ out4)
{
    const float4* y4 = (const float4*)g_y3;
    long total = NCTV/4;
    long stride = (long)gridDim.x*256;
    for (long i = (long)blockIdx.x*256 + threadIdx.x; i < total; i += stride) {
        int o = (int)((i / 1875) & 63);
        float sc = g_stat[128 + o*2 + 0];
        float sf = g_stat[128 + o*2 + 1];
        float4 y = y4[i], xx = x4[i], r;
        r.x = fmaxf(0.f, y.x*sc + sf + xx.x);
        r.y = fmaxf(0.f, y.y*sc + sf + xx.y);
        r.z = fmaxf(0.f, y.z*sc + sf + xx.z);
        r.w = fmaxf(0.f, y.w*sc + sf + xx.w);
        out4[i] = r;
    }
}

// ---------------- launch --------------------------------------------------
extern "C" void kernel_launch(void* const* d_in, const int* in_sizes, int n_in,
                              void* d_out, int out_size)
{
    const float* x    = (const float*)d_in[0];
    const float* adj  = (const float*)d_in[1];
    const float* PA   = (const float*)d_in[2];
    const float* Wa   = (const float*)d_in[3];
    const float* ba   = (const float*)d_in[4];
    const float* Wb   = (const float*)d_in[5];
    const float* bb   = (const float*)d_in[6];
    const float* Wd   = (const float*)d_in[7];
    const float* bd   = (const float*)d_in[8];
    const float* g1   = (const float*)d_in[9];
    const float* b1   = (const float*)d_in[10];
    const float* Wt   = (const float*)d_in[11];
    const float* bt   = (const float*)d_in[12];
    const float* g2   = (const float*)d_in[13];
    const float* b2   = (const float*)d_in[14];
    float* out = (float*)d_out;

    float *pAs, *pAq, *pBs, *pBq;
    cudaGetSymbolAddress((void**)&pAs, g_pA_s);
    cudaGetSymbolAddress((void**)&pAq, g_pA_q);
    cudaGetSymbolAddress((void**)&pBs, g_pB_s);
    cudaGetSymbolAddress((void**)&pBq, g_pB_q);

    const int tcn_smem  = (64*YW + 192) * 4;                 // 150272 B
    const int fg_smem   = (12672 + 96) * 4;                  // 51072 B
    const int gcn_smem  = (64*XW + 64*AW + 2100 + 64) * 4;   // 76816 B
    static int smem_set = 0;
    if (!smem_set) {
        cudaFuncSetAttribute(k_tcn_mma,
                             cudaFuncAttributeMaxDynamicSharedMemorySize, tcn_smem);
        cudaFuncSetAttribute(k_fabgram,
                             cudaFuncAttributeMaxDynamicSharedMemorySize, fg_smem);
        cudaFuncSetAttribute(k_gcn,
                             cudaFuncAttributeMaxDynamicSharedMemorySize, gcn_smem);
        smem_set = 1;
    }

    k_prep_wt<<<72, 256>>>(Wt);
    k_prep_wfab<<<12, 256>>>(Wa, Wb);
    k_prep_wd<<<24, 256>>>(Wd);

    k_fabgram<<<dim3(NSP, NB), 256, fg_smem>>>(x, ba, bb);
    k_gram_final<<<dim3(NB, 3), 128>>>(adj, PA);
    k_gcn<<<dim3(NTT, NB), 256, gcn_smem>>>(x, bd);

    k_bn_final<<<64, 128>>>(g1, b1, pAs, pAq, NPA, 0);

    k_tcn_mma<<<dim3(NTILE, NB), 768, tcn_smem>>>(x, bt);

    k_bn_final<<<64, 128>>>(g2, b2, pBs, pBq, NCTA_B, 1);

    k_bn_apply4<<<8192, 256>>>((const float4*)x, (float4*)out);

    // second tuple element: adj_mat passthrough
    long tail = (long)out_size - (long)NCTV;
    if (tail > 0) {
        long cnt = tail < 1875 ? tail : 1875;
        cudaMemcpyAsync(out + NCTV, d_in[1], cnt * sizeof(float),
                        cudaMemcpyDeviceToDevice);
    }
}